// round 1
// baseline (speedup 1.0000x reference)
#include <cuda_runtime.h>
#include <math.h>

#define Bn 4096
#define INn 1024
#define Hn 1024
#define Fn 128
#define H4n 4096
#define EPS 1e-5f

// Scratch (static __device__ — no allocations allowed)
__device__ float g_scale[Bn * 256];   // [B][2F]: scale_i (0:128), scale_h (128:256)
__device__ float g_U[Bn * 256];       // [B][2F]: u_i*scale_i, u_h*scale_h
__device__ float g_stats[Bn * 4];     // [B][mu_i, rstd_i, mu_h, rstd_h]
__device__ float g_M[2 * Fn * Fn];    // A^T A per path (symmetric)
__device__ float g_cm[2 * Fn];        // column sums of A per path
__device__ float g_cpre[Bn * Hn];     // pre-LN cell state
__device__ float g_oact[Bn * Hn];     // sigmoid(o gate)

// ---------------------------------------------------------------------------
__global__ void k_zero() {
    int i = blockIdx.x * 256 + threadIdx.x;
    if (i < 2 * Fn * Fn) g_M[i] = 0.f;
    if (i < 2 * Fn) g_cm[i] = 0.f;
}

// ---------------------------------------------------------------------------
// scale[b, f] = sum_t (theta(topic)[b,t]) * wb[f,t],  theta = topic @ thw^T + thb
__global__ void k_scales(const float* __restrict__ topic,
                         const float* __restrict__ thiw, const float* __restrict__ thib,
                         const float* __restrict__ thhw, const float* __restrict__ thhb,
                         const float* __restrict__ wib, const float* __restrict__ whb) {
    int b = blockIdx.x;
    int c = threadIdx.x;           // 0..255
    int path = c >> 7, f = c & 127;
    const float* thw = path ? thhw : thiw;
    const float* thb = path ? thhb : thib;
    const float* wb  = path ? whb  : wib;
    float t0 = topic[b * 3 + 0], t1 = topic[b * 3 + 1], t2 = topic[b * 3 + 2];
    float s = 0.f;
#pragma unroll
    for (int t = 0; t < 3; t++) {
        float th = thb[t] + t0 * thw[t * 3 + 0] + t1 * thw[t * 3 + 1] + t2 * thw[t * 3 + 2];
        s += th * wb[f * 3 + t];
    }
    g_scale[b * 256 + c] = s;
}

// ---------------------------------------------------------------------------
// M_p = A_p^T A_p  and column sums, via 32 j-chunks of 128 rows + atomics.
__global__ __launch_bounds__(256) void k_syrk(const float* __restrict__ wia,
                                              const float* __restrict__ wha) {
    int p = blockIdx.y;
    const float* A = p ? wha : wia;   // [4096, 128]
    __shared__ float sA[64 * 128];
    int tid = threadIdx.x;
    int f1 = (tid >> 4) * 8, f2 = (tid & 15) * 8;
    float acc[8][8];
#pragma unroll
    for (int i = 0; i < 8; i++)
#pragma unroll
        for (int k = 0; k < 8; k++) acc[i][k] = 0.f;
    float cs = 0.f;
    for (int jc = 0; jc < 2; jc++) {
        int j0 = blockIdx.x * 128 + jc * 64;
        for (int v = tid; v < 64 * 128 / 4; v += 256)
            ((float4*)sA)[v] = ((const float4*)(A + j0 * 128))[v];
        __syncthreads();
        for (int j = 0; j < 64; j++) {
            float l[8], r[8];
#pragma unroll
            for (int i = 0; i < 8; i++) { l[i] = sA[j * 128 + f1 + i]; r[i] = sA[j * 128 + f2 + i]; }
#pragma unroll
            for (int i = 0; i < 8; i++)
#pragma unroll
                for (int k = 0; k < 8; k++) acc[i][k] += l[i] * r[k];
        }
        if (tid < 128) {
            for (int j = 0; j < 64; j++) cs += sA[j * 128 + tid];
        }
        __syncthreads();
    }
#pragma unroll
    for (int i = 0; i < 8; i++)
#pragma unroll
        for (int k = 0; k < 8; k++)
            atomicAdd(&g_M[p * Fn * Fn + (f1 + i) * Fn + (f2 + k)], acc[i][k]);
    if (tid < 128) atomicAdd(&g_cm[p * Fn + tid], cs);
}

// ---------------------------------------------------------------------------
// U[b, c] = (X @ W^T)[b, f] * scale[b, c].  Tiles: 64 rows x 64 cols, K-chunks 32.
__global__ __launch_bounds__(256) void k_gemm1(const float* __restrict__ xin,
                                               const float* __restrict__ hx,
                                               const float* __restrict__ wic,
                                               const float* __restrict__ whc) {
    int cb = blockIdx.x, rb = blockIdx.y;   // cb: 0..3 (0,1 = i path; 2,3 = h path)
    const float* X = (cb >= 2) ? hx : xin;
    const float* W = (cb >= 2) ? whc : wic;
    int fbase = (cb & 1) * 64;
    __shared__ float sX[64 * 36];
    __shared__ float sWt[32 * 65];          // transposed [k][f] to avoid conflicts
    int tid = threadIdx.x;
    int ty = tid >> 5, tx = tid & 31;
    float acc[8][2];
#pragma unroll
    for (int i = 0; i < 8; i++) { acc[i][0] = 0.f; acc[i][1] = 0.f; }
    for (int ko = 0; ko < 1024; ko += 32) {
#pragma unroll
        for (int r = 0; r < 2; r++) {
            int v = tid + r * 256;
            int row = v >> 3, k4 = v & 7;
            float4 d = *(const float4*)(X + (rb * 64 + row) * 1024 + ko + k4 * 4);
            *(float4*)(sX + row * 36 + k4 * 4) = d;
            float4 e = *(const float4*)(W + (fbase + row) * 1024 + ko + k4 * 4);
            sWt[(k4 * 4 + 0) * 65 + row] = e.x;
            sWt[(k4 * 4 + 1) * 65 + row] = e.y;
            sWt[(k4 * 4 + 2) * 65 + row] = e.z;
            sWt[(k4 * 4 + 3) * 65 + row] = e.w;
        }
        __syncthreads();
#pragma unroll 8
        for (int k = 0; k < 32; k++) {
            float w0 = sWt[k * 65 + tx], w1 = sWt[k * 65 + tx + 32];
#pragma unroll
            for (int i = 0; i < 8; i++) {
                float xv = sX[(ty * 8 + i) * 36 + k];
                acc[i][0] += xv * w0;
                acc[i][1] += xv * w1;
            }
        }
        __syncthreads();
    }
#pragma unroll
    for (int i = 0; i < 8; i++) {
        int row = rb * 64 + ty * 8 + i;
#pragma unroll
        for (int j = 0; j < 2; j++) {
            int cg = cb * 64 + tx + j * 32;
            g_U[row * 256 + cg] = acc[i][j] * g_scale[row * 256 + cg];
        }
    }
}

// ---------------------------------------------------------------------------
// Per-row LN stats of the (virtual) big gate matrices:
//   mu = <u, cm>/4H,  E[x^2] = u^T M u / 4H  (M symmetric -> coalesced column reads)
__global__ __launch_bounds__(128) void k_stats() {
    int b0 = blockIdx.x * 16;
    int t = threadIdx.x;   // 0..127
    __shared__ float su[16 * 256];
    __shared__ float sred[8];
    for (int v = t; v < 16 * 256 / 4; v += 128)
        ((float4*)su)[v] = ((const float4*)(g_U + b0 * 256))[v];
    __syncthreads();
    for (int p = 0; p < 2; p++) {
        float w[16];
#pragma unroll
        for (int r = 0; r < 16; r++) w[r] = 0.f;
        const float* M = g_M + p * Fn * Fn;
        for (int f2 = 0; f2 < 128; f2++) {
            float mc = M[f2 * 128 + t];           // coalesced (M symmetric)
#pragma unroll
            for (int r = 0; r < 16; r++) w[r] += mc * su[r * 256 + p * 128 + f2];
        }
        float cm = g_cm[p * 128 + t];
        for (int r = 0; r < 16; r++) {
            float uv = su[r * 256 + p * 128 + t];
            float q = uv * w[r];
            float dm = uv * cm;
#pragma unroll
            for (int o = 16; o; o >>= 1) {
                q  += __shfl_xor_sync(0xffffffffu, q, o);
                dm += __shfl_xor_sync(0xffffffffu, dm, o);
            }
            int wid = t >> 5, lane = t & 31;
            if (lane == 0) { sred[wid] = q; sred[4 + wid] = dm; }
            __syncthreads();
            if (t == 0) {
                float qs = sred[0] + sred[1] + sred[2] + sred[3];
                float ds = sred[4] + sred[5] + sred[6] + sred[7];
                float mu = ds * (1.f / 4096.f);
                float ex2 = qs * (1.f / 4096.f);
                g_stats[(b0 + r) * 4 + 2 * p] = mu;
                g_stats[(b0 + r) * 4 + 2 * p + 1] = rsqrtf(ex2 - mu * mu + EPS);
            }
            __syncthreads();
        }
    }
}

// ---------------------------------------------------------------------------
// GEMM2 fused: per (64-row, 32-h) tile compute all 8 (path,gate) sub-GEMMs
// (K=128), apply the two LNs via precomputed stats, activations, cell update.
#define SU_STRIDE 260
#define SA_PG 1056   // 32*33, layout [pg][k][c]

__global__ __launch_bounds__(256, 2) void k_gemm2(
    const float* __restrict__ wia, const float* __restrict__ wha,
    const float* __restrict__ liw, const float* __restrict__ lib,
    const float* __restrict__ lhw, const float* __restrict__ lhb,
    const float* __restrict__ cx) {
    extern __shared__ float sm[];
    float* sU = sm;                        // 64 x 260
    float* sA = sm + 64 * SU_STRIDE;       // 8 x 32 x 33
    int tid = threadIdx.x;
    int ty = tid >> 5, tx = tid & 31;
    int hb = blockIdx.x, rb = blockIdx.y;

    // Load full U tile for 64 rows (u_i | u_h)
    {
        const float4* src = (const float4*)(g_U + rb * 64 * 256);
#pragma unroll
        for (int r2 = 0; r2 < 16; r2++) {
            int v = tid + r2 * 256;
            int row = v >> 6, c4 = v & 63;
            float4 d = src[v];
            *(float4*)(sU + row * SU_STRIDE + c4 * 4) = d;
        }
    }

    float acc[8][8];   // [path*4+gate][row_i]
#pragma unroll
    for (int a = 0; a < 8; a++)
#pragma unroll
        for (int b = 0; b < 8; b++) acc[a][b] = 0.f;

    int c = tid >> 3, k4 = tid & 7;
    for (int kc = 0; kc < 4; kc++) {
        // Load A chunk: 8 (path,gate) tiles of [32 rows x 32 k], stored [k][c]
#pragma unroll
        for (int pg = 0; pg < 8; pg++) {
            const float* Ap = (pg < 4) ? wia : wha;
            int gate = pg & 3;
            int j = gate * 1024 + hb * 32 + c;
            float4 d = *(const float4*)(Ap + j * 128 + kc * 32 + k4 * 4);
            float* dst = sA + pg * SA_PG + c;
            dst[(k4 * 4 + 0) * 33] = d.x;
            dst[(k4 * 4 + 1) * 33] = d.y;
            dst[(k4 * 4 + 2) * 33] = d.z;
            dst[(k4 * 4 + 3) * 33] = d.w;
        }
        __syncthreads();
        const float* up = sU + (ty * 8) * SU_STRIDE + kc * 32;
#pragma unroll 8
        for (int kk = 0; kk < 32; kk++) {
            float ui[8], uh[8];
#pragma unroll
            for (int i = 0; i < 8; i++) {
                ui[i] = up[i * SU_STRIDE + kk];
                uh[i] = up[i * SU_STRIDE + 128 + kk];
            }
#pragma unroll
            for (int pg = 0; pg < 4; pg++) {
                float av = sA[pg * SA_PG + kk * 33 + tx];
#pragma unroll
                for (int i = 0; i < 8; i++) acc[pg][i] += ui[i] * av;
            }
#pragma unroll
            for (int pg = 4; pg < 8; pg++) {
                float av = sA[pg * SA_PG + kk * 33 + tx];
#pragma unroll
                for (int i = 0; i < 8; i++) acc[pg][i] += uh[i] * av;
            }
        }
        __syncthreads();
    }

    // Fused epilogue: LN(igates)+LN(hgates), activations, cell update
    int h = hb * 32 + tx;
    float lw[4], lbv[4], hw[4], hbv[4];
#pragma unroll
    for (int g = 0; g < 4; g++) {
        int j = g * 1024 + h;
        lw[g] = liw[j]; lbv[g] = lib[j]; hw[g] = lhw[j]; hbv[g] = lhb[j];
    }
#pragma unroll
    for (int i = 0; i < 8; i++) {
        int row = rb * 64 + ty * 8 + i;
        float mui = g_stats[row * 4 + 0], rsi = g_stats[row * 4 + 1];
        float muh = g_stats[row * 4 + 2], rsh = g_stats[row * 4 + 3];
        float gv[4];
#pragma unroll
        for (int g = 0; g < 4; g++)
            gv[g] = (acc[g][i] - mui) * rsi * lw[g] + lbv[g]
                  + (acc[4 + g][i] - muh) * rsh * hw[g] + hbv[g];
        float ig = 1.f / (1.f + __expf(-gv[0]));
        float fg = 1.f / (1.f + __expf(-gv[1]));
        float gg = tanhf(gv[2]);
        float og = 1.f / (1.f + __expf(-gv[3]));
        float cpre = fg * cx[row * Hn + h] + ig * gg;
        g_cpre[row * Hn + h] = cpre;
        g_oact[row * Hn + h] = og;
    }
}

// ---------------------------------------------------------------------------
// Final LN over H of c_pre, then hy = o * tanh(cy). One CTA per row.
__global__ __launch_bounds__(256) void k_final(const float* __restrict__ lcw,
                                               const float* __restrict__ lcb,
                                               float* __restrict__ out) {
    int b = blockIdx.x, t = threadIdx.x;
    float cl[4];
    float s = 0.f, s2 = 0.f;
#pragma unroll
    for (int i = 0; i < 4; i++) {
        cl[i] = g_cpre[b * Hn + t + i * 256];
        s += cl[i]; s2 += cl[i] * cl[i];
    }
#pragma unroll
    for (int o = 16; o; o >>= 1) {
        s  += __shfl_xor_sync(0xffffffffu, s, o);
        s2 += __shfl_xor_sync(0xffffffffu, s2, o);
    }
    __shared__ float sm1[8], sm2[8], bc[2];
    int wid = t >> 5, lane = t & 31;
    if (lane == 0) { sm1[wid] = s; sm2[wid] = s2; }
    __syncthreads();
    if (t == 0) {
        float ss = 0.f, ss2 = 0.f;
        for (int w = 0; w < 8; w++) { ss += sm1[w]; ss2 += sm2[w]; }
        float mu = ss * (1.f / 1024.f);
        float var = ss2 * (1.f / 1024.f) - mu * mu;
        bc[0] = mu; bc[1] = rsqrtf(var + EPS);
    }
    __syncthreads();
    float mu = bc[0], rstd = bc[1];
#pragma unroll
    for (int i = 0; i < 4; i++) {
        int h = t + i * 256;
        float cy = (cl[i] - mu) * rstd * lcw[h] + lcb[h];
        out[Bn * Hn + b * Hn + h] = cy;                       // cy second
        out[b * Hn + h] = g_oact[b * Hn + h] * tanhf(cy);     // hy first
    }
}

// ---------------------------------------------------------------------------
extern "C" void kernel_launch(void* const* d_in, const int* in_sizes, int n_in,
                              void* d_out, int out_size) {
    const float* input_ = (const float*)d_in[0];
    const float* hx     = (const float*)d_in[1];
    const float* cx     = (const float*)d_in[2];
    const float* topic  = (const float*)d_in[3];
    const float* wia    = (const float*)d_in[4];
    const float* wib    = (const float*)d_in[5];
    const float* wic    = (const float*)d_in[6];
    const float* wha    = (const float*)d_in[7];
    const float* whb    = (const float*)d_in[8];
    const float* whc    = (const float*)d_in[9];
    const float* thiw   = (const float*)d_in[10];
    const float* thib   = (const float*)d_in[11];
    const float* thhw   = (const float*)d_in[12];
    const float* thhb   = (const float*)d_in[13];
    const float* liw    = (const float*)d_in[14];
    const float* lib    = (const float*)d_in[15];
    const float* lhw    = (const float*)d_in[16];
    const float* lhb    = (const float*)d_in[17];
    const float* lcw    = (const float*)d_in[18];
    const float* lcb    = (const float*)d_in[19];
    float* out = (float*)d_out;

    const int smem_bytes = (64 * SU_STRIDE + 8 * SA_PG) * 4;  // 100352 B
    cudaFuncSetAttribute(k_gemm2, cudaFuncAttributeMaxDynamicSharedMemorySize, smem_bytes);

    k_zero<<<128, 256>>>();
    k_scales<<<Bn, 256>>>(topic, thiw, thib, thhw, thhb, wib, whb);
    k_syrk<<<dim3(32, 2), 256>>>(wia, wha);
    k_gemm1<<<dim3(4, 64), 256>>>(input_, hx, wic, whc);
    k_stats<<<256, 128>>>();
    k_gemm2<<<dim3(32, 64), 256, smem_bytes>>>(wia, wha, liw, lib, lhw, lhb, cx);
    k_final<<<Bn, 256>>>(lcw, lcb, out);
}

// round 5
// speedup vs baseline: 1.5176x; 1.5176x over previous
#include <cuda_runtime.h>
#include <cuda_bf16.h>
#include <cstdint>
#include <math.h>

#define Bn 4096
#define INn 1024
#define Hn 1024
#define Fn 128
#define H4n 4096
#define EPS 1e-5f

// Scratch (static __device__ — no allocations allowed)
__device__ float g_scale[Bn * 256];   // [B][2F]: scale_i (0:128), scale_h (128:256)
__device__ float g_U[Bn * 256];       // [B][2F]: u_i*scale_i, u_h*scale_h
__device__ float g_stats[Bn * 4];     // [B][mu_i, rstd_i, mu_h, rstd_h]
__device__ float g_M[2 * Fn * Fn];    // A^T A per path (symmetric)
__device__ float g_cm[2 * Fn];        // column sums of A per path
__device__ float g_cpre[Bn * Hn];     // pre-LN cell state
__device__ float g_oact[Bn * Hn];     // sigmoid(o gate)
// bf16 hi/lo operands for the fused MMA GEMM
__device__ __nv_bfloat16 g_Uh[Bn * 256];    // row-scaled U (rstd folded), hi part
__device__ __nv_bfloat16 g_Ul[Bn * 256];    // lo part
__device__ __nv_bfloat16 g_Wh[H4n * 256];   // permuted, LN-weight-scaled weights, hi
__device__ __nv_bfloat16 g_Wl[H4n * 256];   // lo
__device__ float2 g_a12[Bn];                // {mu_i*rstd_i, mu_h*rstd_h}
__device__ float g_bcomb[H4n];              // lib + lhb

// ============================ PTX helpers ===================================
__device__ __forceinline__ uint32_t smem_u32(const void* p) {
    uint32_t a;
    asm("{ .reg .u64 t; cvta.to.shared.u64 t, %1; cvt.u32.u64 %0, t; }" : "=r"(a) : "l"(p));
    return a;
}
__device__ __forceinline__ void cp_async16(uint32_t dst, const void* src) {
    asm volatile("cp.async.cg.shared.global [%0], [%1], 16;" :: "r"(dst), "l"(src) : "memory");
}
__device__ __forceinline__ void cp_commit() {
    asm volatile("cp.async.commit_group;" ::: "memory");
}
__device__ __forceinline__ void ldsm4(uint32_t* r, uint32_t a) {
    asm volatile("ldmatrix.sync.aligned.m8n8.x4.shared.b16 {%0,%1,%2,%3}, [%4];"
        : "=r"(r[0]), "=r"(r[1]), "=r"(r[2]), "=r"(r[3]) : "r"(a));
}
__device__ __forceinline__ void mma16816(float* d, const uint32_t* a, uint32_t b0, uint32_t b1) {
    asm volatile(
        "mma.sync.aligned.m16n8k16.row.col.f32.bf16.bf16.f32 "
        "{%0,%1,%2,%3}, {%4,%5,%6,%7}, {%8,%9}, {%0,%1,%2,%3};"
        : "+f"(d[0]), "+f"(d[1]), "+f"(d[2]), "+f"(d[3])
        : "r"(a[0]), "r"(a[1]), "r"(a[2]), "r"(a[3]), "r"(b0), "r"(b1));
}

// ---------------------------------------------------------------------------
__global__ void k_zero() {
    int i = blockIdx.x * 256 + threadIdx.x;
    if (i < 2 * Fn * Fn) g_M[i] = 0.f;
    if (i < 2 * Fn) g_cm[i] = 0.f;
}

// ---------------------------------------------------------------------------
__global__ void k_scales(const float* __restrict__ topic,
                         const float* __restrict__ thiw, const float* __restrict__ thib,
                         const float* __restrict__ thhw, const float* __restrict__ thhb,
                         const float* __restrict__ wib, const float* __restrict__ whb) {
    int b = blockIdx.x;
    int c = threadIdx.x;           // 0..255
    int path = c >> 7, f = c & 127;
    const float* thw = path ? thhw : thiw;
    const float* thb = path ? thhb : thib;
    const float* wb  = path ? whb  : wib;
    float t0 = topic[b * 3 + 0], t1 = topic[b * 3 + 1], t2 = topic[b * 3 + 2];
    float s = 0.f;
#pragma unroll
    for (int t = 0; t < 3; t++) {
        float th = thb[t] + t0 * thw[t * 3 + 0] + t1 * thw[t * 3 + 1] + t2 * thw[t * 3 + 2];
        s += th * wb[f * 3 + t];
    }
    g_scale[b * 256 + c] = s;
}

// ---------------------------------------------------------------------------
__global__ __launch_bounds__(256) void k_syrk(const float* __restrict__ wia,
                                              const float* __restrict__ wha) {
    int p = blockIdx.y;
    const float* A = p ? wha : wia;   // [4096, 128]
    __shared__ float sA[64 * 128];
    int tid = threadIdx.x;
    int f1 = (tid >> 4) * 8, f2 = (tid & 15) * 8;
    float acc[8][8];
#pragma unroll
    for (int i = 0; i < 8; i++)
#pragma unroll
        for (int k = 0; k < 8; k++) acc[i][k] = 0.f;
    float cs = 0.f;
    for (int jc = 0; jc < 2; jc++) {
        int j0 = blockIdx.x * 128 + jc * 64;
        for (int v = tid; v < 64 * 128 / 4; v += 256)
            ((float4*)sA)[v] = ((const float4*)(A + j0 * 128))[v];
        __syncthreads();
        for (int j = 0; j < 64; j++) {
            float l[8], r[8];
#pragma unroll
            for (int i = 0; i < 8; i++) { l[i] = sA[j * 128 + f1 + i]; r[i] = sA[j * 128 + f2 + i]; }
#pragma unroll
            for (int i = 0; i < 8; i++)
#pragma unroll
                for (int k = 0; k < 8; k++) acc[i][k] += l[i] * r[k];
        }
        if (tid < 128) {
            for (int j = 0; j < 64; j++) cs += sA[j * 128 + tid];
        }
        __syncthreads();
    }
#pragma unroll
    for (int i = 0; i < 8; i++)
#pragma unroll
        for (int k = 0; k < 8; k++)
            atomicAdd(&g_M[p * Fn * Fn + (f1 + i) * Fn + (f2 + k)], acc[i][k]);
    if (tid < 128) atomicAdd(&g_cm[p * Fn + tid], cs);
}

// ---------------------------------------------------------------------------
__global__ __launch_bounds__(256) void k_gemm1(const float* __restrict__ xin,
                                               const float* __restrict__ hx,
                                               const float* __restrict__ wic,
                                               const float* __restrict__ whc) {
    int cb = blockIdx.x, rb = blockIdx.y;
    const float* X = (cb >= 2) ? hx : xin;
    const float* W = (cb >= 2) ? whc : wic;
    int fbase = (cb & 1) * 64;
    __shared__ float sX[64 * 36];
    __shared__ float sWt[32 * 65];
    int tid = threadIdx.x;
    int ty = tid >> 5, tx = tid & 31;
    float acc[8][2];
#pragma unroll
    for (int i = 0; i < 8; i++) { acc[i][0] = 0.f; acc[i][1] = 0.f; }
    for (int ko = 0; ko < 1024; ko += 32) {
#pragma unroll
        for (int r = 0; r < 2; r++) {
            int v = tid + r * 256;
            int row = v >> 3, k4 = v & 7;
            float4 d = *(const float4*)(X + (rb * 64 + row) * 1024 + ko + k4 * 4);
            *(float4*)(sX + row * 36 + k4 * 4) = d;
            float4 e = *(const float4*)(W + (fbase + row) * 1024 + ko + k4 * 4);
            sWt[(k4 * 4 + 0) * 65 + row] = e.x;
            sWt[(k4 * 4 + 1) * 65 + row] = e.y;
            sWt[(k4 * 4 + 2) * 65 + row] = e.z;
            sWt[(k4 * 4 + 3) * 65 + row] = e.w;
        }
        __syncthreads();
#pragma unroll 8
        for (int k = 0; k < 32; k++) {
            float w0 = sWt[k * 65 + tx], w1 = sWt[k * 65 + tx + 32];
#pragma unroll
            for (int i = 0; i < 8; i++) {
                float xv = sX[(ty * 8 + i) * 36 + k];
                acc[i][0] += xv * w0;
                acc[i][1] += xv * w1;
            }
        }
        __syncthreads();
    }
#pragma unroll
    for (int i = 0; i < 8; i++) {
        int row = rb * 64 + ty * 8 + i;
#pragma unroll
        for (int j = 0; j < 2; j++) {
            int cg = cb * 64 + tx + j * 32;
            g_U[row * 256 + cg] = acc[i][j] * g_scale[row * 256 + cg];
        }
    }
}

// ---------------------------------------------------------------------------
__global__ __launch_bounds__(128) void k_stats() {
    int b0 = blockIdx.x * 16;
    int t = threadIdx.x;   // 0..127
    __shared__ float su[16 * 256];
    __shared__ float sred[8];
    for (int v = t; v < 16 * 256 / 4; v += 128)
        ((float4*)su)[v] = ((const float4*)(g_U + b0 * 256))[v];
    __syncthreads();
    for (int p = 0; p < 2; p++) {
        float w[16];
#pragma unroll
        for (int r = 0; r < 16; r++) w[r] = 0.f;
        const float* M = g_M + p * Fn * Fn;
        for (int f2 = 0; f2 < 128; f2++) {
            float mc = M[f2 * 128 + t];
#pragma unroll
            for (int r = 0; r < 16; r++) w[r] += mc * su[r * 256 + p * 128 + f2];
        }
        float cm = g_cm[p * 128 + t];
        for (int r = 0; r < 16; r++) {
            float uv = su[r * 256 + p * 128 + t];
            float q = uv * w[r];
            float dm = uv * cm;
#pragma unroll
            for (int o = 16; o; o >>= 1) {
                q  += __shfl_xor_sync(0xffffffffu, q, o);
                dm += __shfl_xor_sync(0xffffffffu, dm, o);
            }
            int wid = t >> 5, lane = t & 31;
            if (lane == 0) { sred[wid] = q; sred[4 + wid] = dm; }
            __syncthreads();
            if (t == 0) {
                float qs = sred[0] + sred[1] + sred[2] + sred[3];
                float ds = sred[4] + sred[5] + sred[6] + sred[7];
                float mu = ds * (1.f / 4096.f);
                float ex2 = qs * (1.f / 4096.f);
                g_stats[(b0 + r) * 4 + 2 * p] = mu;
                g_stats[(b0 + r) * 4 + 2 * p + 1] = rsqrtf(ex2 - mu * mu + EPS);
            }
            __syncthreads();
        }
    }
}

// ---------------------------------------------------------------------------
// Prep W: permuted column order C -> j = gate*1024 + h, h = (C>>5)*8 + (C&7),
// gate = (C>>3)&3. Row C of Wcomb: [wia_row*liw | wha_row*lhw], split hi/lo bf16.
__global__ __launch_bounds__(256) void k_prepW(
    const float* __restrict__ wia, const float* __restrict__ wha,
    const float* __restrict__ liw, const float* __restrict__ lhw,
    const float* __restrict__ lib, const float* __restrict__ lhb) {
    int C = blockIdx.x, k = threadIdx.x;   // k 0..255
    int h = ((C >> 5) << 3) + (C & 7);
    int gate = (C >> 3) & 3;
    int j = gate * 1024 + h;
    float v;
    if (k < 128) v = wia[j * 128 + k] * liw[j];
    else         v = wha[j * 128 + (k - 128)] * lhw[j];
    float hi = __bfloat162float(__float2bfloat16(v));
    g_Wh[C * 256 + k] = __float2bfloat16(v);
    g_Wl[C * 256 + k] = __float2bfloat16(v - hi);
    if (k == 0) g_bcomb[j] = lib[j] + lhb[j];
}

// ---------------------------------------------------------------------------
// Prep U: fold rstd into rows of U, split hi/lo bf16; store mu*rstd per row.
__global__ __launch_bounds__(256) void k_prepU() {
    int b = blockIdx.x, k = threadIdx.x;
    float4 st = *(const float4*)(g_stats + b * 4);
    float v = g_U[b * 256 + k] * (k < 128 ? st.y : st.w);
    float hi = __bfloat162float(__float2bfloat16(v));
    g_Uh[b * 256 + k] = __float2bfloat16(v);
    g_Ul[b * 256 + k] = __float2bfloat16(v - hi);
    if (k == 0) g_a12[b] = make_float2(st.x * st.y, st.z * st.w);
}

// ===========================================================================
// GEMM2 via mma.sync bf16 hi/lo (3 passes, K=256 each), fused LSTM epilogue.
// CTA tile 128 rows x 128 C-cols (= 32 h x 4 gates). 8 warps: 2(M) x 4(N),
// warp tile 64x32. TRIPLE-buffered cp.async (prefetch distance 2 needs 3
// stages — 2 stages raced: chunk c+2 overwrote the stage chunk c was reading).
// ===========================================================================
#define G2_STAGE 32768
#define G2_SMEM  (3 * G2_STAGE)   // 96 KB

__global__ __launch_bounds__(256, 2) void k_gemm2_mma(
    const float* __restrict__ liw, const float* __restrict__ lhw,
    const float* __restrict__ cx) {
    extern __shared__ char smem[];
    uint32_t sb = smem_u32(smem);
    const int tid = threadIdx.x, l = tid & 31, wid = tid >> 5;
    const int wm = wid & 1, wn = wid >> 1;
    const int hb = blockIdx.x, rb = blockIdx.y;

    float acc[4][4][4];
#pragma unroll
    for (int a = 0; a < 4; a++)
#pragma unroll
        for (int b = 0; b < 4; b++)
#pragma unroll
            for (int c = 0; c < 4; c++) acc[a][b][c] = 0.f;

    // per-thread load indices (4 x (A,B) 16B per chunk)
    const int lrow = tid >> 3, lch = tid & 7;

#pragma unroll 1
    for (int c = -2; c < 12; c++) {
        // issue chunk c+2 into stage (c+2)%3 (disjoint from stages c, c+1)
        int ci = c + 2;
        if (ci < 12) {
            int p = ci >> 2, kc = ci & 3;
            const __nv_bfloat16* As = (p == 2) ? g_Ul : g_Uh;
            const __nv_bfloat16* Bs = (p == 1) ? g_Wl : g_Wh;
            uint32_t stage = sb + (uint32_t)(ci % 3) * G2_STAGE;
#pragma unroll
            for (int it = 0; it < 4; it++) {
                int row = lrow + it * 32;
                uint32_t soff = (uint32_t)((row * 8 + (lch ^ (row & 7))) << 4);
                cp_async16(stage + soff,
                           As + (rb * 128 + row) * 256 + kc * 64 + lch * 8);
                cp_async16(stage + 16384 + soff,
                           Bs + (hb * 128 + row) * 256 + kc * 64 + lch * 8);
            }
            cp_commit();
        }
        if (c < 0) continue;
        // chunk c complete when pending groups <= (chunks issued after c)
        if (c < 10)      asm volatile("cp.async.wait_group 2;" ::: "memory");
        else if (c == 10) asm volatile("cp.async.wait_group 1;" ::: "memory");
        else             asm volatile("cp.async.wait_group 0;" ::: "memory");
        __syncthreads();

        uint32_t Ab = sb + (uint32_t)(c % 3) * G2_STAGE;
        uint32_t Bb = Ab + 16384;
#pragma unroll
        for (int ks = 0; ks < 4; ks++) {
            uint32_t a[4][4], bu[2][4];
#pragma unroll
            for (int mi = 0; mi < 4; mi++) {
                int r0 = wm * 64 + mi * 16 + ((l >> 3) & 1) * 8 + (l & 7);
                int ch = ks * 2 + (l >> 4);
                ldsm4(a[mi], Ab + (uint32_t)((r0 * 8 + (ch ^ (r0 & 7))) << 4));
            }
#pragma unroll
            for (int nfp = 0; nfp < 2; nfp++) {
                int m = l >> 3;
                int nr = wn * 32 + nfp * 16 + ((m >> 1) << 3) + (l & 7);
                int ch = ks * 2 + (m & 1);
                ldsm4(bu[nfp], Bb + (uint32_t)((nr * 8 + (ch ^ (nr & 7))) << 4));
            }
#pragma unroll
            for (int mi = 0; mi < 4; mi++)
#pragma unroll
                for (int nf = 0; nf < 4; nf++)
                    mma16816(acc[mi][nf], a[mi],
                             bu[nf >> 1][(nf & 1) * 2], bu[nf >> 1][(nf & 1) * 2 + 1]);
        }
        __syncthreads();
    }

    // ---- fused epilogue ----
    const int q = l & 3;
    // column params: h = (hb*4 + wn)*8 + q*2 + e ; j = gate*1024 + h
    float cliw[4][2], clhw[4][2], cbc[4][2];
#pragma unroll
    for (int g = 0; g < 4; g++)
#pragma unroll
        for (int e = 0; e < 2; e++) {
            int h = (hb * 4 + wn) * 8 + q * 2 + e;
            int j = g * 1024 + h;
            cliw[g][e] = liw[j];
            clhw[g][e] = lhw[j];
            cbc[g][e]  = g_bcomb[j];
        }
#pragma unroll
    for (int mi = 0; mi < 4; mi++) {
#pragma unroll
        for (int rs = 0; rs < 2; rs++) {
            int row = rb * 128 + wm * 64 + mi * 16 + (l >> 2) + rs * 8;
            float2 a12 = g_a12[row];
#pragma unroll
            for (int e = 0; e < 2; e++) {
                int h = (hb * 4 + wn) * 8 + q * 2 + e;
                float gv[4];
#pragma unroll
                for (int g = 0; g < 4; g++)
                    gv[g] = acc[mi][g][rs * 2 + e] + cbc[g][e]
                          - a12.x * cliw[g][e] - a12.y * clhw[g][e];
                float ig = 1.f / (1.f + __expf(-gv[0]));
                float fg = 1.f / (1.f + __expf(-gv[1]));
                float gg = tanhf(gv[2]);
                float og = 1.f / (1.f + __expf(-gv[3]));
                float cpre = fg * cx[row * Hn + h] + ig * gg;
                g_cpre[row * Hn + h] = cpre;
                g_oact[row * Hn + h] = og;
            }
        }
    }
}

// ---------------------------------------------------------------------------
__global__ __launch_bounds__(256) void k_final(const float* __restrict__ lcw,
                                               const float* __restrict__ lcb,
                                               float* __restrict__ out) {
    int b = blockIdx.x, t = threadIdx.x;
    float cl[4];
    float s = 0.f, s2 = 0.f;
#pragma unroll
    for (int i = 0; i < 4; i++) {
        cl[i] = g_cpre[b * Hn + t + i * 256];
        s += cl[i]; s2 += cl[i] * cl[i];
    }
#pragma unroll
    for (int o = 16; o; o >>= 1) {
        s  += __shfl_xor_sync(0xffffffffu, s, o);
        s2 += __shfl_xor_sync(0xffffffffu, s2, o);
    }
    __shared__ float sm1[8], sm2[8], bc[2];
    int wid = t >> 5, lane = t & 31;
    if (lane == 0) { sm1[wid] = s; sm2[wid] = s2; }
    __syncthreads();
    if (t == 0) {
        float ss = 0.f, ss2 = 0.f;
        for (int w = 0; w < 8; w++) { ss += sm1[w]; ss2 += sm2[w]; }
        float mu = ss * (1.f / 1024.f);
        float var = ss2 * (1.f / 1024.f) - mu * mu;
        bc[0] = mu; bc[1] = rsqrtf(var + EPS);
    }
    __syncthreads();
    float mu = bc[0], rstd = bc[1];
#pragma unroll
    for (int i = 0; i < 4; i++) {
        int h = t + i * 256;
        float cy = (cl[i] - mu) * rstd * lcw[h] + lcb[h];
        out[Bn * Hn + b * Hn + h] = cy;
        out[b * Hn + h] = g_oact[b * Hn + h] * tanhf(cy);
    }
}

// ---------------------------------------------------------------------------
extern "C" void kernel_launch(void* const* d_in, const int* in_sizes, int n_in,
                              void* d_out, int out_size) {
    const float* input_ = (const float*)d_in[0];
    const float* hx     = (const float*)d_in[1];
    const float* cx     = (const float*)d_in[2];
    const float* topic  = (const float*)d_in[3];
    const float* wia    = (const float*)d_in[4];
    const float* wib    = (const float*)d_in[5];
    const float* wic    = (const float*)d_in[6];
    const float* wha    = (const float*)d_in[7];
    const float* whb    = (const float*)d_in[8];
    const float* whc    = (const float*)d_in[9];
    const float* thiw   = (const float*)d_in[10];
    const float* thib   = (const float*)d_in[11];
    const float* thhw   = (const float*)d_in[12];
    const float* thhb   = (const float*)d_in[13];
    const float* liw    = (const float*)d_in[14];
    const float* lib    = (const float*)d_in[15];
    const float* lhw    = (const float*)d_in[16];
    const float* lhb    = (const float*)d_in[17];
    const float* lcw    = (const float*)d_in[18];
    const float* lcb    = (const float*)d_in[19];
    float* out = (float*)d_out;

    cudaFuncSetAttribute(k_gemm2_mma, cudaFuncAttributeMaxDynamicSharedMemorySize, G2_SMEM);

    k_zero<<<128, 256>>>();
    k_scales<<<Bn, 256>>>(topic, thiw, thib, thhw, thhb, wib, whb);
    k_syrk<<<dim3(32, 2), 256>>>(wia, wha);
    k_prepW<<<H4n, 256>>>(wia, wha, liw, lhw, lib, lhb);
    k_gemm1<<<dim3(4, 64), 256>>>(input_, hx, wic, whc);
    k_stats<<<256, 128>>>();
    k_prepU<<<Bn, 256>>>();
    k_gemm2_mma<<<dim3(32, 32), 256, G2_SMEM>>>(liw, lhw, cx);
    k_final<<<Bn, 256>>>(lcw, lcb, out);
}

// round 6
// speedup vs baseline: 1.7163x; 1.1309x over previous
#include <cuda_runtime.h>
#include <cuda_bf16.h>
#include <cstdint>
#include <math.h>

#define Bn 4096
#define INn 1024
#define Hn 1024
#define Fn 128
#define H4n 4096
#define EPS 1e-5f

// Scratch (static __device__ — no allocations allowed)
__device__ float g_scale[Bn * 256];   // [B][2F]: scale_i (0:128), scale_h (128:256)
__device__ float g_U[Bn * 256];       // [B][2F]: u_i*scale_i, u_h*scale_h (fp32)
__device__ float g_M[2 * Fn * Fn];    // A^T A per path (symmetric)
__device__ float g_cm[2 * Fn];        // column sums of A per path
__device__ float g_cpre[Bn * Hn];     // pre-LN cell state
__device__ float g_oact[Bn * Hn];     // sigmoid(o gate)
// bf16 hi/lo operands
__device__ __nv_bfloat16 g_Uh[Bn * 256];    // row-scaled U (rstd folded), hi
__device__ __nv_bfloat16 g_Ul[Bn * 256];    // lo
__device__ __nv_bfloat16 g_Wh[H4n * 256];   // permuted, LN-weight-scaled weights, hi
__device__ __nv_bfloat16 g_Wl[H4n * 256];   // lo
__device__ __nv_bfloat16 g_Xh[2 * Bn * INn];  // [path][B,1024] x/hx hi
__device__ __nv_bfloat16 g_Xl[2 * Bn * INn];  // lo
__device__ __nv_bfloat16 g_Vh[2 * Fn * INn];  // [path][128,1024] wic/whc hi
__device__ __nv_bfloat16 g_Vl[2 * Fn * INn];  // lo
__device__ float2 g_a12[Bn];                // {mu_i*rstd_i, mu_h*rstd_h}
__device__ float g_bcomb[H4n];              // lib + lhb

// ============================ PTX helpers ===================================
__device__ __forceinline__ uint32_t smem_u32(const void* p) {
    uint32_t a;
    asm("{ .reg .u64 t; cvta.to.shared.u64 t, %1; cvt.u32.u64 %0, t; }" : "=r"(a) : "l"(p));
    return a;
}
__device__ __forceinline__ void cp_async16(uint32_t dst, const void* src) {
    asm volatile("cp.async.cg.shared.global [%0], [%1], 16;" :: "r"(dst), "l"(src) : "memory");
}
__device__ __forceinline__ void cp_commit() {
    asm volatile("cp.async.commit_group;" ::: "memory");
}
__device__ __forceinline__ void ldsm4(uint32_t* r, uint32_t a) {
    asm volatile("ldmatrix.sync.aligned.m8n8.x4.shared.b16 {%0,%1,%2,%3}, [%4];"
        : "=r"(r[0]), "=r"(r[1]), "=r"(r[2]), "=r"(r[3]) : "r"(a));
}
__device__ __forceinline__ void mma16816(float* d, const uint32_t* a, uint32_t b0, uint32_t b1) {
    asm volatile(
        "mma.sync.aligned.m16n8k16.row.col.f32.bf16.bf16.f32 "
        "{%0,%1,%2,%3}, {%4,%5,%6,%7}, {%8,%9}, {%0,%1,%2,%3};"
        : "+f"(d[0]), "+f"(d[1]), "+f"(d[2]), "+f"(d[3])
        : "r"(a[0]), "r"(a[1]), "r"(a[2]), "r"(a[3]), "r"(b0), "r"(b1));
}
__device__ __forceinline__ uint2 split_pack4(float4 d, uint2& lo) {
    __nv_bfloat16 h0 = __float2bfloat16(d.x), h1 = __float2bfloat16(d.y);
    __nv_bfloat16 h2 = __float2bfloat16(d.z), h3 = __float2bfloat16(d.w);
    __nv_bfloat16 l0 = __float2bfloat16(d.x - __bfloat162float(h0));
    __nv_bfloat16 l1 = __float2bfloat16(d.y - __bfloat162float(h1));
    __nv_bfloat16 l2 = __float2bfloat16(d.z - __bfloat162float(h2));
    __nv_bfloat16 l3 = __float2bfloat16(d.w - __bfloat162float(h3));
    uint2 hi;
    hi.x = (uint32_t)__bfloat16_as_ushort(h0) | ((uint32_t)__bfloat16_as_ushort(h1) << 16);
    hi.y = (uint32_t)__bfloat16_as_ushort(h2) | ((uint32_t)__bfloat16_as_ushort(h3) << 16);
    lo.x = (uint32_t)__bfloat16_as_ushort(l0) | ((uint32_t)__bfloat16_as_ushort(l1) << 16);
    lo.y = (uint32_t)__bfloat16_as_ushort(l2) | ((uint32_t)__bfloat16_as_ushort(l3) << 16);
    return hi;
}

// ---------------------------------------------------------------------------
__global__ void k_zero() {
    int i = blockIdx.x * 256 + threadIdx.x;
    if (i < 2 * Fn * Fn) g_M[i] = 0.f;
    if (i < 2 * Fn) g_cm[i] = 0.f;
}

// ---------------------------------------------------------------------------
__global__ void k_scales(const float* __restrict__ topic,
                         const float* __restrict__ thiw, const float* __restrict__ thib,
                         const float* __restrict__ thhw, const float* __restrict__ thhb,
                         const float* __restrict__ wib, const float* __restrict__ whb) {
    int b = blockIdx.x;
    int c = threadIdx.x;           // 0..255
    int path = c >> 7, f = c & 127;
    const float* thw = path ? thhw : thiw;
    const float* thb = path ? thhb : thib;
    const float* wb  = path ? whb  : wib;
    float t0 = topic[b * 3 + 0], t1 = topic[b * 3 + 1], t2 = topic[b * 3 + 2];
    float s = 0.f;
#pragma unroll
    for (int t = 0; t < 3; t++) {
        float th = thb[t] + t0 * thw[t * 3 + 0] + t1 * thw[t * 3 + 1] + t2 * thw[t * 3 + 2];
        s += th * wb[f * 3 + t];
    }
    g_scale[b * 256 + c] = s;
}

// ---------------------------------------------------------------------------
// Split x / hx into bf16 hi/lo.
__global__ __launch_bounds__(256) void k_prepX(const float* __restrict__ xin,
                                               const float* __restrict__ hx) {
    int p = blockIdx.y;
    const float* src = p ? hx : xin;
    int base = blockIdx.x * 1024 + threadIdx.x * 4;   // 4096 blocks cover 4M elems
    float4 d = *(const float4*)(src + base);
    uint2 lo, hi = split_pack4(d, lo);
    *(uint2*)(g_Xh + p * (Bn * INn) + base) = hi;
    *(uint2*)(g_Xl + p * (Bn * INn) + base) = lo;
}

// Split wic / whc into bf16 hi/lo.
__global__ __launch_bounds__(256) void k_prepWc(const float* __restrict__ wic,
                                                const float* __restrict__ whc) {
    int p = blockIdx.y;
    const float* src = p ? whc : wic;
    int base = blockIdx.x * 1024 + threadIdx.x * 4;   // 128 blocks cover 128K elems
    float4 d = *(const float4*)(src + base);
    uint2 lo, hi = split_pack4(d, lo);
    *(uint2*)(g_Vh + p * (Fn * INn) + base) = hi;
    *(uint2*)(g_Vl + p * (Fn * INn) + base) = lo;
}

// ---------------------------------------------------------------------------
__global__ __launch_bounds__(256) void k_syrk(const float* __restrict__ wia,
                                              const float* __restrict__ wha) {
    int p = blockIdx.y;
    const float* A = p ? wha : wia;   // [4096, 128]
    __shared__ float sA[64 * 128];
    int tid = threadIdx.x;
    int f1 = (tid >> 4) * 8, f2 = (tid & 15) * 8;
    float acc[8][8];
#pragma unroll
    for (int i = 0; i < 8; i++)
#pragma unroll
        for (int k = 0; k < 8; k++) acc[i][k] = 0.f;
    float cs = 0.f;
    for (int jc = 0; jc < 2; jc++) {
        int j0 = blockIdx.x * 128 + jc * 64;
        for (int v = tid; v < 64 * 128 / 4; v += 256)
            ((float4*)sA)[v] = ((const float4*)(A + j0 * 128))[v];
        __syncthreads();
        for (int j = 0; j < 64; j++) {
            float l[8], r[8];
#pragma unroll
            for (int i = 0; i < 8; i++) { l[i] = sA[j * 128 + f1 + i]; r[i] = sA[j * 128 + f2 + i]; }
#pragma unroll
            for (int i = 0; i < 8; i++)
#pragma unroll
                for (int k = 0; k < 8; k++) acc[i][k] += l[i] * r[k];
        }
        if (tid < 128) {
            for (int j = 0; j < 64; j++) cs += sA[j * 128 + tid];
        }
        __syncthreads();
    }
#pragma unroll
    for (int i = 0; i < 8; i++)
#pragma unroll
        for (int k = 0; k < 8; k++)
            atomicAdd(&g_M[p * Fn * Fn + (f1 + i) * Fn + (f2 + k)], acc[i][k]);
    if (tid < 128) atomicAdd(&g_cm[p * Fn + tid], cs);
}

// ===========================================================================
// GEMM1 via mma.sync bf16 hi/lo: U[b,f] = (X @ W^T)*scale, per path.
// CTA 64(M) x 64(N), K=1024 in 16 chunks of 64. 4 warps, warp tile 32x32.
// All 3 hi/lo combos per chunk (operands read once). 2-stage, distance-1.
// Stage: Ah(8K) Al(8K) Bh(8K) Bl(8K) = 32KB; 2 stages = 64KB.
// ===========================================================================
#define G1_STAGE 32768
#define G1_SMEM  (2 * G1_STAGE)

__global__ __launch_bounds__(128, 3) void k_gemm1_mma() {
    extern __shared__ char smem[];
    uint32_t sb = smem_u32(smem);
    const int tid = threadIdx.x, l = tid & 31, wid = tid >> 5;
    const int wm = wid & 1, wn = wid >> 1;
    const int nb = blockIdx.x, rb = blockIdx.y, p = blockIdx.z;
    const __nv_bfloat16* Xh = g_Xh + p * (Bn * INn);
    const __nv_bfloat16* Xl = g_Xl + p * (Bn * INn);
    const __nv_bfloat16* Vh = g_Vh + p * (Fn * INn);
    const __nv_bfloat16* Vl = g_Vl + p * (Fn * INn);

    float acc[2][4][4];
#pragma unroll
    for (int a = 0; a < 2; a++)
#pragma unroll
        for (int b = 0; b < 4; b++)
#pragma unroll
            for (int c = 0; c < 4; c++) acc[a][b][c] = 0.f;

    // loader: 128 threads, per array 512 16B-chunks -> 4 per thread
    const int lrow = tid >> 1, lch0 = (tid & 1) * 4;   // rows 0..63, chunks {0..3|4..7}

#pragma unroll 1
    for (int cc = -1; cc < 16; cc++) {
        int ci = cc + 1;
        if (ci < 16) {
            uint32_t stage = sb + (uint32_t)(ci & 1) * G1_STAGE;
            const __nv_bfloat16* Asrc = Xh + (rb * 64 + lrow) * 1024 + ci * 64 + lch0 * 8;
            const __nv_bfloat16* Alsrc = Xl + (rb * 64 + lrow) * 1024 + ci * 64 + lch0 * 8;
            const __nv_bfloat16* Bsrc = Vh + (nb * 64 + lrow) * 1024 + ci * 64 + lch0 * 8;
            const __nv_bfloat16* Blsrc = Vl + (nb * 64 + lrow) * 1024 + ci * 64 + lch0 * 8;
#pragma unroll
            for (int q = 0; q < 4; q++) {
                int ch = lch0 + q;
                uint32_t soff = (uint32_t)((lrow * 8 + (ch ^ (lrow & 7))) << 4);
                cp_async16(stage + soff,         Asrc + q * 8);
                cp_async16(stage + 8192 + soff,  Alsrc + q * 8);
                cp_async16(stage + 16384 + soff, Bsrc + q * 8);
                cp_async16(stage + 24576 + soff, Blsrc + q * 8);
            }
            cp_commit();
        }
        if (cc < 0) continue;
        if (cc < 15) asm volatile("cp.async.wait_group 1;" ::: "memory");
        else         asm volatile("cp.async.wait_group 0;" ::: "memory");
        __syncthreads();

        uint32_t Ah = sb + (uint32_t)(cc & 1) * G1_STAGE;
        uint32_t Al = Ah + 8192, Bh = Ah + 16384, Bl = Ah + 24576;
#pragma unroll
        for (int ks = 0; ks < 4; ks++) {
            uint32_t ah[2][4], al[2][4], bh[2][4], bl[2][4];
#pragma unroll
            for (int mi = 0; mi < 2; mi++) {
                int r0 = wm * 32 + mi * 16 + ((l >> 3) & 1) * 8 + (l & 7);
                int ch = ks * 2 + (l >> 4);
                uint32_t soff = (uint32_t)((r0 * 8 + (ch ^ (r0 & 7))) << 4);
                ldsm4(ah[mi], Ah + soff);
                ldsm4(al[mi], Al + soff);
            }
#pragma unroll
            for (int nfp = 0; nfp < 2; nfp++) {
                int m = l >> 3;
                int nr = wn * 32 + nfp * 16 + ((m >> 1) << 3) + (l & 7);
                int ch = ks * 2 + (m & 1);
                uint32_t soff = (uint32_t)((nr * 8 + (ch ^ (nr & 7))) << 4);
                ldsm4(bh[nfp], Bh + soff);
                ldsm4(bl[nfp], Bl + soff);
            }
#pragma unroll
            for (int mi = 0; mi < 2; mi++)
#pragma unroll
                for (int nf = 0; nf < 4; nf++) {
                    uint32_t b0h = bh[nf >> 1][(nf & 1) * 2], b1h = bh[nf >> 1][(nf & 1) * 2 + 1];
                    uint32_t b0l = bl[nf >> 1][(nf & 1) * 2], b1l = bl[nf >> 1][(nf & 1) * 2 + 1];
                    mma16816(acc[mi][nf], ah[mi], b0h, b1h);
                    mma16816(acc[mi][nf], ah[mi], b0l, b1l);
                    mma16816(acc[mi][nf], al[mi], b0h, b1h);
                }
        }
        __syncthreads();
    }

    // epilogue: multiply by scale, write g_U fp32
#pragma unroll
    for (int mi = 0; mi < 2; mi++)
#pragma unroll
        for (int rs = 0; rs < 2; rs++) {
            int row = rb * 64 + wm * 32 + mi * 16 + (l >> 2) + rs * 8;
#pragma unroll
            for (int nf = 0; nf < 4; nf++)
#pragma unroll
                for (int e = 0; e < 2; e++) {
                    int fcol = nb * 64 + wn * 32 + nf * 8 + (l & 3) * 2 + e;
                    int idx = row * 256 + p * 128 + fcol;
                    g_U[idx] = acc[mi][nf][rs * 2 + e] * g_scale[idx];
                }
        }
}

// ---------------------------------------------------------------------------
// LN stats via quadratic form + fused prep of Uh/Ul (rstd folded) and a12.
__global__ __launch_bounds__(128) void k_stats() {
    int b0 = blockIdx.x * 16;
    int t = threadIdx.x;   // 0..127
    __shared__ float su[16 * 256];
    __shared__ float sred[8];
    __shared__ float sstat[16][4];
    for (int v = t; v < 16 * 256 / 4; v += 128)
        ((float4*)su)[v] = ((const float4*)(g_U + b0 * 256))[v];
    __syncthreads();
    for (int p = 0; p < 2; p++) {
        float w[16];
#pragma unroll
        for (int r = 0; r < 16; r++) w[r] = 0.f;
        const float* M = g_M + p * Fn * Fn;
        for (int f2 = 0; f2 < 128; f2++) {
            float mc = M[f2 * 128 + t];
#pragma unroll
            for (int r = 0; r < 16; r++) w[r] += mc * su[r * 256 + p * 128 + f2];
        }
        float cm = g_cm[p * 128 + t];
        for (int r = 0; r < 16; r++) {
            float uv = su[r * 256 + p * 128 + t];
            float q = uv * w[r];
            float dm = uv * cm;
#pragma unroll
            for (int o = 16; o; o >>= 1) {
                q  += __shfl_xor_sync(0xffffffffu, q, o);
                dm += __shfl_xor_sync(0xffffffffu, dm, o);
            }
            int wid = t >> 5, lane = t & 31;
            if (lane == 0) { sred[wid] = q; sred[4 + wid] = dm; }
            __syncthreads();
            if (t == 0) {
                float qs = sred[0] + sred[1] + sred[2] + sred[3];
                float ds = sred[4] + sred[5] + sred[6] + sred[7];
                float mu = ds * (1.f / 4096.f);
                float ex2 = qs * (1.f / 4096.f);
                sstat[r][2 * p] = mu;
                sstat[r][2 * p + 1] = rsqrtf(ex2 - mu * mu + EPS);
            }
            __syncthreads();
        }
    }
    // fused prepU: fold rstd, split hi/lo
    for (int r = 0; r < 16; r++) {
        float rsi = sstat[r][1], rsh = sstat[r][3];
#pragma unroll
        for (int half = 0; half < 2; half++) {
            int c = t + half * 128;
            float v = su[r * 256 + c] * (c < 128 ? rsi : rsh);
            float hi = __bfloat162float(__float2bfloat16(v));
            g_Uh[(b0 + r) * 256 + c] = __float2bfloat16(v);
            g_Ul[(b0 + r) * 256 + c] = __float2bfloat16(v - hi);
        }
    }
    if (t < 16)
        g_a12[b0 + t] = make_float2(sstat[t][0] * sstat[t][1], sstat[t][2] * sstat[t][3]);
}

// ---------------------------------------------------------------------------
// Prep W: permuted column order C -> j = gate*1024 + h, h = (C>>5)*8 + (C&7),
// gate = (C>>3)&3. Row C of Wcomb: [wia_row*liw | wha_row*lhw], split hi/lo bf16.
__global__ __launch_bounds__(256) void k_prepW(
    const float* __restrict__ wia, const float* __restrict__ wha,
    const float* __restrict__ liw, const float* __restrict__ lhw,
    const float* __restrict__ lib, const float* __restrict__ lhb) {
    int C = blockIdx.x, k = threadIdx.x;   // k 0..255
    int h = ((C >> 5) << 3) + (C & 7);
    int gate = (C >> 3) & 3;
    int j = gate * 1024 + h;
    float v;
    if (k < 128) v = wia[j * 128 + k] * liw[j];
    else         v = wha[j * 128 + (k - 128)] * lhw[j];
    float hi = __bfloat162float(__float2bfloat16(v));
    g_Wh[C * 256 + k] = __float2bfloat16(v);
    g_Wl[C * 256 + k] = __float2bfloat16(v - hi);
    if (k == 0) g_bcomb[j] = lib[j] + lhb[j];
}

// ===========================================================================
// GEMM2 via mma.sync bf16 hi/lo (3 passes, K=256 each), fused LSTM epilogue.
// CTA tile 128 rows x 128 C-cols. 8 warps 2(M)x4(N), warp tile 64x32.
// Triple-buffered cp.async, distance-2 prefetch.
// ===========================================================================
#define G2_STAGE 32768
#define G2_SMEM  (3 * G2_STAGE)   // 96 KB

__global__ __launch_bounds__(256, 2) void k_gemm2_mma(
    const float* __restrict__ liw, const float* __restrict__ lhw,
    const float* __restrict__ cx) {
    extern __shared__ char smem[];
    uint32_t sb = smem_u32(smem);
    const int tid = threadIdx.x, l = tid & 31, wid = tid >> 5;
    const int wm = wid & 1, wn = wid >> 1;
    const int hb = blockIdx.x, rb = blockIdx.y;

    float acc[4][4][4];
#pragma unroll
    for (int a = 0; a < 4; a++)
#pragma unroll
        for (int b = 0; b < 4; b++)
#pragma unroll
            for (int c = 0; c < 4; c++) acc[a][b][c] = 0.f;

    const int lrow = tid >> 3, lch = tid & 7;

#pragma unroll 1
    for (int c = -2; c < 12; c++) {
        int ci = c + 2;
        if (ci < 12) {
            int p = ci >> 2, kc = ci & 3;
            const __nv_bfloat16* As = (p == 2) ? g_Ul : g_Uh;
            const __nv_bfloat16* Bs = (p == 1) ? g_Wl : g_Wh;
            uint32_t stage = sb + (uint32_t)(ci % 3) * G2_STAGE;
#pragma unroll
            for (int it = 0; it < 4; it++) {
                int row = lrow + it * 32;
                uint32_t soff = (uint32_t)((row * 8 + (lch ^ (row & 7))) << 4);
                cp_async16(stage + soff,
                           As + (rb * 128 + row) * 256 + kc * 64 + lch * 8);
                cp_async16(stage + 16384 + soff,
                           Bs + (hb * 128 + row) * 256 + kc * 64 + lch * 8);
            }
            cp_commit();
        }
        if (c < 0) continue;
        if (c < 10)       asm volatile("cp.async.wait_group 2;" ::: "memory");
        else if (c == 10) asm volatile("cp.async.wait_group 1;" ::: "memory");
        else              asm volatile("cp.async.wait_group 0;" ::: "memory");
        __syncthreads();

        uint32_t Ab = sb + (uint32_t)(c % 3) * G2_STAGE;
        uint32_t Bb = Ab + 16384;
#pragma unroll
        for (int ks = 0; ks < 4; ks++) {
            uint32_t a[4][4], bu[2][4];
#pragma unroll
            for (int mi = 0; mi < 4; mi++) {
                int r0 = wm * 64 + mi * 16 + ((l >> 3) & 1) * 8 + (l & 7);
                int ch = ks * 2 + (l >> 4);
                ldsm4(a[mi], Ab + (uint32_t)((r0 * 8 + (ch ^ (r0 & 7))) << 4));
            }
#pragma unroll
            for (int nfp = 0; nfp < 2; nfp++) {
                int m = l >> 3;
                int nr = wn * 32 + nfp * 16 + ((m >> 1) << 3) + (l & 7);
                int ch = ks * 2 + (m & 1);
                ldsm4(bu[nfp], Bb + (uint32_t)((nr * 8 + (ch ^ (nr & 7))) << 4));
            }
#pragma unroll
            for (int mi = 0; mi < 4; mi++)
#pragma unroll
                for (int nf = 0; nf < 4; nf++)
                    mma16816(acc[mi][nf], a[mi],
                             bu[nf >> 1][(nf & 1) * 2], bu[nf >> 1][(nf & 1) * 2 + 1]);
        }
        __syncthreads();
    }

    // ---- fused epilogue ----
    const int q = l & 3;
    float cliw[4][2], clhw[4][2], cbc[4][2];
#pragma unroll
    for (int g = 0; g < 4; g++)
#pragma unroll
        for (int e = 0; e < 2; e++) {
            int h = (hb * 4 + wn) * 8 + q * 2 + e;
            int j = g * 1024 + h;
            cliw[g][e] = liw[j];
            clhw[g][e] = lhw[j];
            cbc[g][e]  = g_bcomb[j];
        }
#pragma unroll
    for (int mi = 0; mi < 4; mi++) {
#pragma unroll
        for (int rs = 0; rs < 2; rs++) {
            int row = rb * 128 + wm * 64 + mi * 16 + (l >> 2) + rs * 8;
            float2 a12 = g_a12[row];
#pragma unroll
            for (int e = 0; e < 2; e++) {
                int h = (hb * 4 + wn) * 8 + q * 2 + e;
                float gv[4];
#pragma unroll
                for (int g = 0; g < 4; g++)
                    gv[g] = acc[mi][g][rs * 2 + e] + cbc[g][e]
                          - a12.x * cliw[g][e] - a12.y * clhw[g][e];
                float ig = 1.f / (1.f + __expf(-gv[0]));
                float fg = 1.f / (1.f + __expf(-gv[1]));
                float gg = tanhf(gv[2]);
                float og = 1.f / (1.f + __expf(-gv[3]));
                float cpre = fg * cx[row * Hn + h] + ig * gg;
                g_cpre[row * Hn + h] = cpre;
                g_oact[row * Hn + h] = og;
            }
        }
    }
}

// ---------------------------------------------------------------------------
__global__ __launch_bounds__(256) void k_final(const float* __restrict__ lcw,
                                               const float* __restrict__ lcb,
                                               float* __restrict__ out) {
    int b = blockIdx.x, t = threadIdx.x;
    float cl[4];
    float s = 0.f, s2 = 0.f;
#pragma unroll
    for (int i = 0; i < 4; i++) {
        cl[i] = g_cpre[b * Hn + t + i * 256];
        s += cl[i]; s2 += cl[i] * cl[i];
    }
#pragma unroll
    for (int o = 16; o; o >>= 1) {
        s  += __shfl_xor_sync(0xffffffffu, s, o);
        s2 += __shfl_xor_sync(0xffffffffu, s2, o);
    }
    __shared__ float sm1[8], sm2[8], bc[2];
    int wid = t >> 5, lane = t & 31;
    if (lane == 0) { sm1[wid] = s; sm2[wid] = s2; }
    __syncthreads();
    if (t == 0) {
        float ss = 0.f, ss2 = 0.f;
        for (int w = 0; w < 8; w++) { ss += sm1[w]; ss2 += sm2[w]; }
        float mu = ss * (1.f / 1024.f);
        float var = ss2 * (1.f / 1024.f) - mu * mu;
        bc[0] = mu; bc[1] = rsqrtf(var + EPS);
    }
    __syncthreads();
    float mu = bc[0], rstd = bc[1];
#pragma unroll
    for (int i = 0; i < 4; i++) {
        int h = t + i * 256;
        float cy = (cl[i] - mu) * rstd * lcw[h] + lcb[h];
        out[Bn * Hn + b * Hn + h] = cy;
        out[b * Hn + h] = g_oact[b * Hn + h] * tanhf(cy);
    }
}

// ---------------------------------------------------------------------------
extern "C" void kernel_launch(void* const* d_in, const int* in_sizes, int n_in,
                              void* d_out, int out_size) {
    const float* input_ = (const float*)d_in[0];
    const float* hx     = (const float*)d_in[1];
    const float* cx     = (const float*)d_in[2];
    const float* topic  = (const float*)d_in[3];
    const float* wia    = (const float*)d_in[4];
    const float* wib    = (const float*)d_in[5];
    const float* wic    = (const float*)d_in[6];
    const float* wha    = (const float*)d_in[7];
    const float* whb    = (const float*)d_in[8];
    const float* whc    = (const float*)d_in[9];
    const float* thiw   = (const float*)d_in[10];
    const float* thib   = (const float*)d_in[11];
    const float* thhw   = (const float*)d_in[12];
    const float* thhb   = (const float*)d_in[13];
    const float* liw    = (const float*)d_in[14];
    const float* lib    = (const float*)d_in[15];
    const float* lhw    = (const float*)d_in[16];
    const float* lhb    = (const float*)d_in[17];
    const float* lcw    = (const float*)d_in[18];
    const float* lcb    = (const float*)d_in[19];
    float* out = (float*)d_out;

    cudaFuncSetAttribute(k_gemm1_mma, cudaFuncAttributeMaxDynamicSharedMemorySize, G1_SMEM);
    cudaFuncSetAttribute(k_gemm2_mma, cudaFuncAttributeMaxDynamicSharedMemorySize, G2_SMEM);

    k_zero<<<128, 256>>>();
    k_scales<<<Bn, 256>>>(topic, thiw, thib, thhw, thhb, wib, whb);
    k_prepX<<<dim3(4096, 2), 256>>>(input_, hx);
    k_prepWc<<<dim3(128, 2), 256>>>(wic, whc);
    k_syrk<<<dim3(32, 2), 256>>>(wia, wha);
    k_prepW<<<H4n, 256>>>(wia, wha, liw, lhw, lib, lhb);
    k_gemm1_mma<<<dim3(2, 64, 2), 128, G1_SMEM>>>();
    k_stats<<<256, 128>>>();
    k_gemm2_mma<<<dim3(32, 32), 256, G2_SMEM>>>(liw, lhw, cx);
    k_final<<<Bn, 256>>>(lcw, lcb, out);
}

// round 9
// speedup vs baseline: 1.8475x; 1.0765x over previous
#include <cuda_runtime.h>
#include <cuda_bf16.h>
#include <cstdint>
#include <math.h>

#define Bn 4096
#define INn 1024
#define Hn 1024
#define Fn 128
#define H4n 4096
#define EPS 1e-5f

// Scratch (static __device__ — no allocations allowed)
__device__ float g_scale[Bn * 256];   // [B][2F]: scale_i (0:128), scale_h (128:256)
__device__ float g_U[Bn * 256];       // [B][2F]: u_i*scale_i, u_h*scale_h (fp32)
__device__ float g_M[2 * Fn * Fn];    // A^T A per path (symmetric)
__device__ float g_cm[2 * Fn];        // column sums of A per path
__device__ float g_cpre[Bn * Hn];     // pre-LN cell state
__device__ float g_oact[Bn * Hn];     // sigmoid(o gate)
// bf16 hi/lo operands
__device__ __nv_bfloat16 g_Uh[Bn * 256];    // row-scaled U (rstd folded), hi
__device__ __nv_bfloat16 g_Ul[Bn * 256];    // lo
__device__ __nv_bfloat16 g_Wh[H4n * 256];   // permuted, LN-weight-scaled weights, hi
__device__ __nv_bfloat16 g_Wl[H4n * 256];   // lo
__device__ __nv_bfloat16 g_Xh[2 * Bn * INn];  // [path][B,1024] x/hx hi
__device__ __nv_bfloat16 g_Xl[2 * Bn * INn];  // lo
__device__ __nv_bfloat16 g_Vh[2 * Fn * INn];  // [path][128,1024] wic/whc hi
__device__ __nv_bfloat16 g_Vl[2 * Fn * INn];  // lo
__device__ float2 g_a12[Bn];                // {mu_i*rstd_i, mu_h*rstd_h}
__device__ float g_bcomb[H4n];              // lib + lhb

// ============================ PTX helpers ===================================
__device__ __forceinline__ uint32_t smem_u32(const void* p) {
    uint32_t a;
    asm("{ .reg .u64 t; cvta.to.shared.u64 t, %1; cvt.u32.u64 %0, t; }" : "=r"(a) : "l"(p));
    return a;
}
__device__ __forceinline__ void cp_async16(uint32_t dst, const void* src) {
    asm volatile("cp.async.cg.shared.global [%0], [%1], 16;" :: "r"(dst), "l"(src) : "memory");
}
__device__ __forceinline__ void cp_commit() {
    asm volatile("cp.async.commit_group;" ::: "memory");
}
__device__ __forceinline__ void ldsm4(uint32_t* r, uint32_t a) {
    asm volatile("ldmatrix.sync.aligned.m8n8.x4.shared.b16 {%0,%1,%2,%3}, [%4];"
        : "=r"(r[0]), "=r"(r[1]), "=r"(r[2]), "=r"(r[3]) : "r"(a));
}
__device__ __forceinline__ void mma16816(float* d, const uint32_t* a, uint32_t b0, uint32_t b1) {
    asm volatile(
        "mma.sync.aligned.m16n8k16.row.col.f32.bf16.bf16.f32 "
        "{%0,%1,%2,%3}, {%4,%5,%6,%7}, {%8,%9}, {%0,%1,%2,%3};"
        : "+f"(d[0]), "+f"(d[1]), "+f"(d[2]), "+f"(d[3])
        : "r"(a[0]), "r"(a[1]), "r"(a[2]), "r"(a[3]), "r"(b0), "r"(b1));
}
__device__ __forceinline__ uint2 split_pack4(float4 d, uint2& lo) {
    __nv_bfloat16 h0 = __float2bfloat16(d.x), h1 = __float2bfloat16(d.y);
    __nv_bfloat16 h2 = __float2bfloat16(d.z), h3 = __float2bfloat16(d.w);
    __nv_bfloat16 l0 = __float2bfloat16(d.x - __bfloat162float(h0));
    __nv_bfloat16 l1 = __float2bfloat16(d.y - __bfloat162float(h1));
    __nv_bfloat16 l2 = __float2bfloat16(d.z - __bfloat162float(h2));
    __nv_bfloat16 l3 = __float2bfloat16(d.w - __bfloat162float(h3));
    uint2 hi;
    hi.x = (uint32_t)__bfloat16_as_ushort(h0) | ((uint32_t)__bfloat16_as_ushort(h1) << 16);
    hi.y = (uint32_t)__bfloat16_as_ushort(h2) | ((uint32_t)__bfloat16_as_ushort(h3) << 16);
    lo.x = (uint32_t)__bfloat16_as_ushort(l0) | ((uint32_t)__bfloat16_as_ushort(l1) << 16);
    lo.y = (uint32_t)__bfloat16_as_ushort(l2) | ((uint32_t)__bfloat16_as_ushort(l3) << 16);
    return hi;
}

// ---------------------------------------------------------------------------
__global__ void k_zero() {
    int i = blockIdx.x * 256 + threadIdx.x;
    if (i < 2 * Fn * Fn) g_M[i] = 0.f;
    if (i < 2 * Fn) g_cm[i] = 0.f;
}

// ---------------------------------------------------------------------------
__global__ void k_scales(const float* __restrict__ topic,
                         const float* __restrict__ thiw, const float* __restrict__ thib,
                         const float* __restrict__ thhw, const float* __restrict__ thhb,
                         const float* __restrict__ wib, const float* __restrict__ whb) {
    int b = blockIdx.x;
    int c = threadIdx.x;           // 0..255
    int path = c >> 7, f = c & 127;
    const float* thw = path ? thhw : thiw;
    const float* thb = path ? thhb : thib;
    const float* wb  = path ? whb  : wib;
    float t0 = topic[b * 3 + 0], t1 = topic[b * 3 + 1], t2 = topic[b * 3 + 2];
    float s = 0.f;
#pragma unroll
    for (int t = 0; t < 3; t++) {
        float th = thb[t] + t0 * thw[t * 3 + 0] + t1 * thw[t * 3 + 1] + t2 * thw[t * 3 + 2];
        s += th * wb[f * 3 + t];
    }
    g_scale[b * 256 + c] = s;
}

// ---------------------------------------------------------------------------
// Split x / hx into bf16 hi/lo.
__global__ __launch_bounds__(256) void k_prepX(const float* __restrict__ xin,
                                               const float* __restrict__ hx) {
    int p = blockIdx.y;
    const float* src = p ? hx : xin;
    int base = blockIdx.x * 1024 + threadIdx.x * 4;
    float4 d = *(const float4*)(src + base);
    uint2 lo, hi = split_pack4(d, lo);
    *(uint2*)(g_Xh + p * (Bn * INn) + base) = hi;
    *(uint2*)(g_Xl + p * (Bn * INn) + base) = lo;
}

// Split wic / whc into bf16 hi/lo.
__global__ __launch_bounds__(256) void k_prepWc(const float* __restrict__ wic,
                                                const float* __restrict__ whc) {
    int p = blockIdx.y;
    const float* src = p ? whc : wic;
    int base = blockIdx.x * 1024 + threadIdx.x * 4;
    float4 d = *(const float4*)(src + base);
    uint2 lo, hi = split_pack4(d, lo);
    *(uint2*)(g_Vh + p * (Fn * INn) + base) = hi;
    *(uint2*)(g_Vl + p * (Fn * INn) + base) = lo;
}

// ---------------------------------------------------------------------------
__global__ __launch_bounds__(256) void k_syrk(const float* __restrict__ wia,
                                              const float* __restrict__ wha) {
    int p = blockIdx.y;
    const float* A = p ? wha : wia;   // [4096, 128]
    __shared__ float sA[64 * 128];
    int tid = threadIdx.x;
    int f1 = (tid >> 4) * 8, f2 = (tid & 15) * 8;
    float acc[8][8];
#pragma unroll
    for (int i = 0; i < 8; i++)
#pragma unroll
        for (int k = 0; k < 8; k++) acc[i][k] = 0.f;
    float cs = 0.f;
    for (int jc = 0; jc < 2; jc++) {
        int j0 = blockIdx.x * 128 + jc * 64;
        for (int v = tid; v < 64 * 128 / 4; v += 256)
            ((float4*)sA)[v] = ((const float4*)(A + j0 * 128))[v];
        __syncthreads();
        for (int j = 0; j < 64; j++) {
            float l[8], r[8];
#pragma unroll
            for (int i = 0; i < 8; i++) { l[i] = sA[j * 128 + f1 + i]; r[i] = sA[j * 128 + f2 + i]; }
#pragma unroll
            for (int i = 0; i < 8; i++)
#pragma unroll
                for (int k = 0; k < 8; k++) acc[i][k] += l[i] * r[k];
        }
        if (tid < 128) {
            for (int j = 0; j < 64; j++) cs += sA[j * 128 + tid];
        }
        __syncthreads();
    }
#pragma unroll
    for (int i = 0; i < 8; i++)
#pragma unroll
        for (int k = 0; k < 8; k++)
            atomicAdd(&g_M[p * Fn * Fn + (f1 + i) * Fn + (f2 + k)], acc[i][k]);
    if (tid < 128) atomicAdd(&g_cm[p * Fn + tid], cs);
}

// ===========================================================================
// GEMM1 via mma.sync bf16 hi/lo: U[b,f] = (X @ W^T)*scale, per path.
// CTA 64(M) x 128(N=all F) — X tile read ONCE. K=1024 in 16 chunks of 64.
// 8 warps 2(M)x4(N), warp tile 32x32. All 3 combos per chunk. 2-stage dist-1.
// Stage: Ah(8K) Al(8K) Bh(16K) Bl(16K) = 48KB; 2 stages = 96KB.
// ===========================================================================
#define G1_STAGE 49152
#define G1_SMEM  (2 * G1_STAGE)

__global__ __launch_bounds__(256, 2) void k_gemm1_mma() {
    extern __shared__ char smem[];
    uint32_t sb = smem_u32(smem);
    const int tid = threadIdx.x, l = tid & 31, wid = tid >> 5;
    const int wm = wid & 1, wn = wid >> 1;
    const int rb = blockIdx.x, p = blockIdx.y;
    const __nv_bfloat16* Xh = g_Xh + p * (Bn * INn);
    const __nv_bfloat16* Xl = g_Xl + p * (Bn * INn);
    const __nv_bfloat16* Vh = g_Vh + p * (Fn * INn);
    const __nv_bfloat16* Vl = g_Vl + p * (Fn * INn);

    float acc[2][4][4];
#pragma unroll
    for (int a = 0; a < 2; a++)
#pragma unroll
        for (int b = 0; b < 4; b++)
#pragma unroll
            for (int c = 0; c < 4; c++) acc[a][b][c] = 0.f;

#pragma unroll 1
    for (int cc = -1; cc < 16; cc++) {
        int ci = cc + 1;
        if (ci < 16) {
            uint32_t stage = sb + (uint32_t)(ci & 1) * G1_STAGE;
#pragma unroll
            for (int it = 0; it < 2; it++) {         // A: 64 rows x 8 ch
                int v = tid + it * 256;
                int row = v >> 3, ch = v & 7;
                uint32_t soff = (uint32_t)((row * 8 + (ch ^ (row & 7))) << 4);
                cp_async16(stage + soff,        Xh + (rb * 64 + row) * 1024 + ci * 64 + ch * 8);
                cp_async16(stage + 8192 + soff, Xl + (rb * 64 + row) * 1024 + ci * 64 + ch * 8);
            }
#pragma unroll
            for (int it = 0; it < 4; it++) {         // B: 128 rows x 8 ch
                int v = tid + it * 256;
                int row = v >> 3, ch = v & 7;
                uint32_t soff = (uint32_t)((row * 8 + (ch ^ (row & 7))) << 4);
                cp_async16(stage + 16384 + soff, Vh + row * 1024 + ci * 64 + ch * 8);
                cp_async16(stage + 32768 + soff, Vl + row * 1024 + ci * 64 + ch * 8);
            }
            cp_commit();
        }
        if (cc < 0) continue;
        if (cc < 15) asm volatile("cp.async.wait_group 1;" ::: "memory");
        else         asm volatile("cp.async.wait_group 0;" ::: "memory");
        __syncthreads();

        uint32_t Ah = sb + (uint32_t)(cc & 1) * G1_STAGE;
        uint32_t Al = Ah + 8192, Bh = Ah + 16384, Bl = Ah + 32768;
#pragma unroll
        for (int ks = 0; ks < 4; ks++) {
            uint32_t a[2][4], bh[2][4], bl[2][4];
#pragma unroll
            for (int mi = 0; mi < 2; mi++) {
                int r0 = wm * 32 + mi * 16 + ((l >> 3) & 1) * 8 + (l & 7);
                int ch = ks * 2 + (l >> 4);
                ldsm4(a[mi], Ah + (uint32_t)((r0 * 8 + (ch ^ (r0 & 7))) << 4));
            }
#pragma unroll
            for (int nfp = 0; nfp < 2; nfp++) {
                int m = l >> 3;
                int nr = wn * 32 + nfp * 16 + ((m >> 1) << 3) + (l & 7);
                int ch = ks * 2 + (m & 1);
                uint32_t soff = (uint32_t)((nr * 8 + (ch ^ (nr & 7))) << 4);
                ldsm4(bh[nfp], Bh + soff);
                ldsm4(bl[nfp], Bl + soff);
            }
#pragma unroll
            for (int mi = 0; mi < 2; mi++)
#pragma unroll
                for (int nf = 0; nf < 4; nf++) {
                    mma16816(acc[mi][nf], a[mi], bh[nf >> 1][(nf & 1) * 2], bh[nf >> 1][(nf & 1) * 2 + 1]);
                    mma16816(acc[mi][nf], a[mi], bl[nf >> 1][(nf & 1) * 2], bl[nf >> 1][(nf & 1) * 2 + 1]);
                }
#pragma unroll
            for (int mi = 0; mi < 2; mi++) {         // reload A as lo, reuse regs
                int r0 = wm * 32 + mi * 16 + ((l >> 3) & 1) * 8 + (l & 7);
                int ch = ks * 2 + (l >> 4);
                ldsm4(a[mi], Al + (uint32_t)((r0 * 8 + (ch ^ (r0 & 7))) << 4));
            }
#pragma unroll
            for (int mi = 0; mi < 2; mi++)
#pragma unroll
                for (int nf = 0; nf < 4; nf++)
                    mma16816(acc[mi][nf], a[mi], bh[nf >> 1][(nf & 1) * 2], bh[nf >> 1][(nf & 1) * 2 + 1]);
        }
        __syncthreads();
    }

    // epilogue: multiply by scale, write g_U fp32
#pragma unroll
    for (int mi = 0; mi < 2; mi++)
#pragma unroll
        for (int rs = 0; rs < 2; rs++) {
            int row = rb * 64 + wm * 32 + mi * 16 + (l >> 2) + rs * 8;
#pragma unroll
            for (int nf = 0; nf < 4; nf++)
#pragma unroll
                for (int e = 0; e < 2; e++) {
                    int fcol = wn * 32 + nf * 8 + (l & 3) * 2 + e;
                    int idx = row * 256 + p * 128 + fcol;
                    g_U[idx] = acc[mi][nf][rs * 2 + e] * g_scale[idx];
                }
        }
}

// ---------------------------------------------------------------------------
// LN stats via quadratic form + fused prep of Uh/Ul (rstd folded) and a12.
__global__ __launch_bounds__(128) void k_stats() {
    int b0 = blockIdx.x * 16;
    int t = threadIdx.x;   // 0..127
    __shared__ float su[16 * 256];
    __shared__ float sred[8];
    __shared__ float sstat[16][4];
    for (int v = t; v < 16 * 256 / 4; v += 128)
        ((float4*)su)[v] = ((const float4*)(g_U + b0 * 256))[v];
    __syncthreads();
    for (int p = 0; p < 2; p++) {
        float w[16];
#pragma unroll
        for (int r = 0; r < 16; r++) w[r] = 0.f;
        const float* M = g_M + p * Fn * Fn;
        for (int f2 = 0; f2 < 128; f2++) {
            float mc = M[f2 * 128 + t];
#pragma unroll
            for (int r = 0; r < 16; r++) w[r] += mc * su[r * 256 + p * 128 + f2];
        }
        float cm = g_cm[p * 128 + t];
        for (int r = 0; r < 16; r++) {
            float uv = su[r * 256 + p * 128 + t];
            float q = uv * w[r];
            float dm = uv * cm;
#pragma unroll
            for (int o = 16; o; o >>= 1) {
                q  += __shfl_xor_sync(0xffffffffu, q, o);
                dm += __shfl_xor_sync(0xffffffffu, dm, o);
            }
            int wid = t >> 5, lane = t & 31;
            if (lane == 0) { sred[wid] = q; sred[4 + wid] = dm; }
            __syncthreads();
            if (t == 0) {
                float qs = sred[0] + sred[1] + sred[2] + sred[3];
                float ds = sred[4] + sred[5] + sred[6] + sred[7];
                float mu = ds * (1.f / 4096.f);
                float ex2 = qs * (1.f / 4096.f);
                sstat[r][2 * p] = mu;
                sstat[r][2 * p + 1] = rsqrtf(ex2 - mu * mu + EPS);
            }
            __syncthreads();
        }
    }
    // fused prepU: fold rstd, split hi/lo
    for (int r = 0; r < 16; r++) {
        float rsi = sstat[r][1], rsh = sstat[r][3];
#pragma unroll
        for (int half = 0; half < 2; half++) {
            int c = t + half * 128;
            float v = su[r * 256 + c] * (c < 128 ? rsi : rsh);
            float hi = __bfloat162float(__float2bfloat16(v));
            g_Uh[(b0 + r) * 256 + c] = __float2bfloat16(v);
            g_Ul[(b0 + r) * 256 + c] = __float2bfloat16(v - hi);
        }
    }
    if (t < 16)
        g_a12[b0 + t] = make_float2(sstat[t][0] * sstat[t][1], sstat[t][2] * sstat[t][3]);
}

// ---------------------------------------------------------------------------
// Prep W: permuted column order C -> j = gate*1024 + h, h = (C>>5)*8 + (C&7),
// gate = (C>>3)&3. Row C of Wcomb: [wia_row*liw | wha_row*lhw], split hi/lo bf16.
__global__ __launch_bounds__(256) void k_prepW(
    const float* __restrict__ wia, const float* __restrict__ wha,
    const float* __restrict__ liw, const float* __restrict__ lhw,
    const float* __restrict__ lib, const float* __restrict__ lhb) {
    int C = blockIdx.x, k = threadIdx.x;   // k 0..255
    int h = ((C >> 5) << 3) + (C & 7);
    int gate = (C >> 3) & 3;
    int j = gate * 1024 + h;
    float v;
    if (k < 128) v = wia[j * 128 + k] * liw[j];
    else         v = wha[j * 128 + (k - 128)] * lhw[j];
    float hi = __bfloat162float(__float2bfloat16(v));
    g_Wh[C * 256 + k] = __float2bfloat16(v);
    g_Wl[C * 256 + k] = __float2bfloat16(v - hi);
    if (k == 0) g_bcomb[j] = lib[j] + lhb[j];
}

// ===========================================================================
// GEMM2 via mma.sync bf16 hi/lo — single-load K-chunks: Ah/Al/Bh/Bl loaded
// ONCE per K=32 chunk (8 chunks), 3 combos in-loop. 64B-row swizzle.
// CTA 128x128, 8 warps 2(M)x4(N), warp 64x32. 3 stages, distance-2.
// Stage: 4 x (128 rows x 64B) = 32KB.
// ===========================================================================
#define G2_STAGE 32768
#define G2_SMEM  (3 * G2_STAGE)   // 96 KB

__global__ __launch_bounds__(256, 2) void k_gemm2_mma(
    const float* __restrict__ liw, const float* __restrict__ lhw,
    const float* __restrict__ cx) {
    extern __shared__ char smem[];
    uint32_t sb = smem_u32(smem);
    const int tid = threadIdx.x, l = tid & 31, wid = tid >> 5;
    const int wm = wid & 1, wn = wid >> 1;
    const int hb = blockIdx.x, rb = blockIdx.y;

    float acc[4][4][4];
#pragma unroll
    for (int a = 0; a < 4; a++)
#pragma unroll
        for (int b = 0; b < 4; b++)
#pragma unroll
            for (int c = 0; c < 4; c++) acc[a][b][c] = 0.f;

#pragma unroll 1
    for (int c = -2; c < 8; c++) {
        int ci = c + 2;
        if (ci < 8) {
            uint32_t stage = sb + (uint32_t)(ci % 3) * G2_STAGE;
#pragma unroll
            for (int it = 0; it < 2; it++) {   // per array: 128 rows x 4 ch(16B)
                int v = tid + it * 256;
                int row = v >> 2, ch = v & 3;
                uint32_t soff = (uint32_t)((row * 4 + (ch ^ ((row >> 1) & 3))) << 4);
                cp_async16(stage + soff,         g_Uh + (rb * 128 + row) * 256 + ci * 32 + ch * 8);
                cp_async16(stage + 8192 + soff,  g_Ul + (rb * 128 + row) * 256 + ci * 32 + ch * 8);
                cp_async16(stage + 16384 + soff, g_Wh + (hb * 128 + row) * 256 + ci * 32 + ch * 8);
                cp_async16(stage + 24576 + soff, g_Wl + (hb * 128 + row) * 256 + ci * 32 + ch * 8);
            }
            cp_commit();
        }
        if (c < 0) continue;
        if (c < 6)       asm volatile("cp.async.wait_group 2;" ::: "memory");
        else if (c == 6) asm volatile("cp.async.wait_group 1;" ::: "memory");
        else             asm volatile("cp.async.wait_group 0;" ::: "memory");
        __syncthreads();

        uint32_t Ah = sb + (uint32_t)(c % 3) * G2_STAGE;
        uint32_t Al = Ah + 8192, Bh = Ah + 16384, Bl = Ah + 24576;
#pragma unroll
        for (int ks = 0; ks < 2; ks++) {
            uint32_t a[4][4], bh[2][4], bl[2][4];
#pragma unroll
            for (int mi = 0; mi < 4; mi++) {
                int r0 = wm * 64 + mi * 16 + ((l >> 3) & 1) * 8 + (l & 7);
                int ch = ks * 2 + (l >> 4);
                ldsm4(a[mi], Ah + (uint32_t)((r0 * 4 + (ch ^ ((r0 >> 1) & 3))) << 4));
            }
#pragma unroll
            for (int nfp = 0; nfp < 2; nfp++) {
                int m = l >> 3;
                int nr = wn * 32 + nfp * 16 + ((m >> 1) << 3) + (l & 7);
                int ch = ks * 2 + (m & 1);
                uint32_t soff = (uint32_t)((nr * 4 + (ch ^ ((nr >> 1) & 3))) << 4);
                ldsm4(bh[nfp], Bh + soff);
                ldsm4(bl[nfp], Bl + soff);
            }
#pragma unroll
            for (int mi = 0; mi < 4; mi++)
#pragma unroll
                for (int nf = 0; nf < 4; nf++) {
                    mma16816(acc[mi][nf], a[mi], bh[nf >> 1][(nf & 1) * 2], bh[nf >> 1][(nf & 1) * 2 + 1]);
                    mma16816(acc[mi][nf], a[mi], bl[nf >> 1][(nf & 1) * 2], bl[nf >> 1][(nf & 1) * 2 + 1]);
                }
#pragma unroll
            for (int mi = 0; mi < 4; mi++) {   // reload A as lo, reuse regs
                int r0 = wm * 64 + mi * 16 + ((l >> 3) & 1) * 8 + (l & 7);
                int ch = ks * 2 + (l >> 4);
                ldsm4(a[mi], Al + (uint32_t)((r0 * 4 + (ch ^ ((r0 >> 1) & 3))) << 4));
            }
#pragma unroll
            for (int mi = 0; mi < 4; mi++)
#pragma unroll
                for (int nf = 0; nf < 4; nf++)
                    mma16816(acc[mi][nf], a[mi], bh[nf >> 1][(nf & 1) * 2], bh[nf >> 1][(nf & 1) * 2 + 1]);
        }
        __syncthreads();
    }

    // ---- fused epilogue ----
    const int q = l & 3;
    float cliw[4][2], clhw[4][2], cbc[4][2];
#pragma unroll
    for (int g = 0; g < 4; g++)
#pragma unroll
        for (int e = 0; e < 2; e++) {
            int h = (hb * 4 + wn) * 8 + q * 2 + e;
            int j = g * 1024 + h;
            cliw[g][e] = liw[j];
            clhw[g][e] = lhw[j];
            cbc[g][e]  = g_bcomb[j];
        }
#pragma unroll
    for (int mi = 0; mi < 4; mi++) {
#pragma unroll
        for (int rs = 0; rs < 2; rs++) {
            int row = rb * 128 + wm * 64 + mi * 16 + (l >> 2) + rs * 8;
            float2 a12 = g_a12[row];
#pragma unroll
            for (int e = 0; e < 2; e++) {
                int h = (hb * 4 + wn) * 8 + q * 2 + e;
                float gv[4];
#pragma unroll
                for (int g = 0; g < 4; g++)
                    gv[g] = acc[mi][g][rs * 2 + e] + cbc[g][e]
                          - a12.x * cliw[g][e] - a12.y * clhw[g][e];
                float ig = 1.f / (1.f + __expf(-gv[0]));
                float fg = 1.f / (1.f + __expf(-gv[1]));
                float gg = tanhf(gv[2]);
                float og = 1.f / (1.f + __expf(-gv[3]));
                float cpre = fg * cx[row * Hn + h] + ig * gg;
                g_cpre[row * Hn + h] = cpre;
                g_oact[row * Hn + h] = og;
            }
        }
    }
}

// ---------------------------------------------------------------------------
__global__ __launch_bounds__(256) void k_final(const float* __restrict__ lcw,
                                               const float* __restrict__ lcb,
                                               float* __restrict__ out) {
    int b = blockIdx.x, t = threadIdx.x;
    float cl[4];
    float s = 0.f, s2 = 0.f;
#pragma unroll
    for (int i = 0; i < 4; i++) {
        cl[i] = g_cpre[b * Hn + t + i * 256];
        s += cl[i]; s2 += cl[i] * cl[i];
    }
#pragma unroll
    for (int o = 16; o; o >>= 1) {
        s  += __shfl_xor_sync(0xffffffffu, s, o);
        s2 += __shfl_xor_sync(0xffffffffu, s2, o);
    }
    __shared__ float sm1[8], sm2[8], bc[2];
    int wid = t >> 5, lane = t & 31;
    if (lane == 0) { sm1[wid] = s; sm2[wid] = s2; }
    __syncthreads();
    if (t == 0) {
        float ss = 0.f, ss2 = 0.f;
        for (int w = 0; w < 8; w++) { ss += sm1[w]; ss2 += sm2[w]; }
        float mu = ss * (1.f / 1024.f);
        float var = ss2 * (1.f / 1024.f) - mu * mu;
        bc[0] = mu; bc[1] = rsqrtf(var + EPS);
    }
    __syncthreads();
    float mu = bc[0], rstd = bc[1];
#pragma unroll
    for (int i = 0; i < 4; i++) {
        int h = t + i * 256;
        float cy = (cl[i] - mu) * rstd * lcw[h] + lcb[h];
        out[Bn * Hn + b * Hn + h] = cy;
        out[b * Hn + h] = g_oact[b * Hn + h] * tanhf(cy);
    }
}

// ---------------------------------------------------------------------------
extern "C" void kernel_launch(void* const* d_in, const int* in_sizes, int n_in,
                              void* d_out, int out_size) {
    const float* input_ = (const float*)d_in[0];
    const float* hx     = (const float*)d_in[1];
    const float* cx     = (const float*)d_in[2];
    const float* topic  = (const float*)d_in[3];
    const float* wia    = (const float*)d_in[4];
    const float* wib    = (const float*)d_in[5];
    const float* wic    = (const float*)d_in[6];
    const float* wha    = (const float*)d_in[7];
    const float* whb    = (const float*)d_in[8];
    const float* whc    = (const float*)d_in[9];
    const float* thiw   = (const float*)d_in[10];
    const float* thib   = (const float*)d_in[11];
    const float* thhw   = (const float*)d_in[12];
    const float* thhb   = (const float*)d_in[13];
    const float* liw    = (const float*)d_in[14];
    const float* lib    = (const float*)d_in[15];
    const float* lhw    = (const float*)d_in[16];
    const float* lhb    = (const float*)d_in[17];
    const float* lcw    = (const float*)d_in[18];
    const float* lcb    = (const float*)d_in[19];
    float* out = (float*)d_out;

    cudaFuncSetAttribute(k_gemm1_mma, cudaFuncAttributeMaxDynamicSharedMemorySize, G1_SMEM);
    cudaFuncSetAttribute(k_gemm2_mma, cudaFuncAttributeMaxDynamicSharedMemorySize, G2_SMEM);

    k_zero<<<128, 256>>>();
    k_scales<<<Bn, 256>>>(topic, thiw, thib, thhw, thhb, wib, whb);
    k_prepX<<<dim3(4096, 2), 256>>>(input_, hx);
    k_prepWc<<<dim3(128, 2), 256>>>(wic, whc);
    k_syrk<<<dim3(32, 2), 256>>>(wia, wha);
    k_prepW<<<H4n, 256>>>(wia, wha, liw, lhw, lib, lhb);
    k_gemm1_mma<<<dim3(64, 2), 256, G1_SMEM>>>();
    k_stats<<<256, 128>>>();
    k_gemm2_mma<<<dim3(32, 32), 256, G2_SMEM>>>(liw, lhw, cx);
    k_final<<<Bn, 256>>>(lcw, lcb, out);
}

// round 10
// speedup vs baseline: 1.9162x; 1.0372x over previous
#include <cuda_runtime.h>
#include <cuda_bf16.h>
#include <cstdint>
#include <math.h>

#define Bn 4096
#define INn 1024
#define Hn 1024
#define Fn 128
#define H4n 4096
#define EPS 1e-5f

// Scratch (static __device__ — no allocations allowed)
__device__ float g_scale[Bn * 256];   // [B][2F]: scale_i (0:128), scale_h (128:256)
__device__ float g_U[Bn * 256];       // [B][2F]: u_i*scale_i, u_h*scale_h (fp32)
__device__ float g_M[2 * Fn * Fn];    // A^T A per path (symmetric)
__device__ float g_cm[2 * Fn];        // column sums of A per path
__device__ float g_cpre[Bn * Hn];     // pre-LN cell state
__device__ float g_oact[Bn * Hn];     // sigmoid(o gate)
// bf16 hi/lo operands
__device__ __nv_bfloat16 g_Uh[Bn * 256];    // row-scaled U (rstd folded), hi
__device__ __nv_bfloat16 g_Ul[Bn * 256];    // lo
__device__ __nv_bfloat16 g_Wh[H4n * 256];   // permuted, LN-weight-scaled weights, hi
__device__ __nv_bfloat16 g_Wl[H4n * 256];   // lo
__device__ __nv_bfloat16 g_Xh[2 * Bn * INn];  // [path][B,1024] x/hx hi
__device__ __nv_bfloat16 g_Xl[2 * Bn * INn];  // lo
__device__ __nv_bfloat16 g_Vh[2 * Fn * INn];  // [path][128,1024] wic/whc hi
__device__ __nv_bfloat16 g_Vl[2 * Fn * INn];  // lo
__device__ float2 g_a12[Bn];                // {mu_i*rstd_i, mu_h*rstd_h}
__device__ float g_bcomb[H4n];              // lib + lhb

// ============================ PTX helpers ===================================
__device__ __forceinline__ uint32_t smem_u32(const void* p) {
    uint32_t a;
    asm("{ .reg .u64 t; cvta.to.shared.u64 t, %1; cvt.u32.u64 %0, t; }" : "=r"(a) : "l"(p));
    return a;
}
__device__ __forceinline__ void cp_async16(uint32_t dst, const void* src) {
    asm volatile("cp.async.cg.shared.global [%0], [%1], 16;" :: "r"(dst), "l"(src) : "memory");
}
__device__ __forceinline__ void cp_commit() {
    asm volatile("cp.async.commit_group;" ::: "memory");
}
__device__ __forceinline__ void ldsm4(uint32_t* r, uint32_t a) {
    asm volatile("ldmatrix.sync.aligned.m8n8.x4.shared.b16 {%0,%1,%2,%3}, [%4];"
        : "=r"(r[0]), "=r"(r[1]), "=r"(r[2]), "=r"(r[3]) : "r"(a));
}
__device__ __forceinline__ void mma16816(float* d, const uint32_t* a, uint32_t b0, uint32_t b1) {
    asm volatile(
        "mma.sync.aligned.m16n8k16.row.col.f32.bf16.bf16.f32 "
        "{%0,%1,%2,%3}, {%4,%5,%6,%7}, {%8,%9}, {%0,%1,%2,%3};"
        : "+f"(d[0]), "+f"(d[1]), "+f"(d[2]), "+f"(d[3])
        : "r"(a[0]), "r"(a[1]), "r"(a[2]), "r"(a[3]), "r"(b0), "r"(b1));
}
__device__ __forceinline__ uint2 split_pack4(float4 d, uint2& lo) {
    __nv_bfloat16 h0 = __float2bfloat16(d.x), h1 = __float2bfloat16(d.y);
    __nv_bfloat16 h2 = __float2bfloat16(d.z), h3 = __float2bfloat16(d.w);
    __nv_bfloat16 l0 = __float2bfloat16(d.x - __bfloat162float(h0));
    __nv_bfloat16 l1 = __float2bfloat16(d.y - __bfloat162float(h1));
    __nv_bfloat16 l2 = __float2bfloat16(d.z - __bfloat162float(h2));
    __nv_bfloat16 l3 = __float2bfloat16(d.w - __bfloat162float(h3));
    uint2 hi;
    hi.x = (uint32_t)__bfloat16_as_ushort(h0) | ((uint32_t)__bfloat16_as_ushort(h1) << 16);
    hi.y = (uint32_t)__bfloat16_as_ushort(h2) | ((uint32_t)__bfloat16_as_ushort(h3) << 16);
    lo.x = (uint32_t)__bfloat16_as_ushort(l0) | ((uint32_t)__bfloat16_as_ushort(l1) << 16);
    lo.y = (uint32_t)__bfloat16_as_ushort(l2) | ((uint32_t)__bfloat16_as_ushort(l3) << 16);
    return hi;
}

// ===========================================================================
// Merged prep: zero(128) | scales(4096) | prepX(8192) | prepWc(256) | prepW(4096)
// dispatched by blockIdx.x range. All parts independent; bodies verbatim from
// the previously-passing separate kernels.
// ===========================================================================
#define PB_ZERO   128
#define PB_SCALES (PB_ZERO + 4096)
#define PB_PREPX  (PB_SCALES + 8192)
#define PB_PREPWC (PB_PREPX + 256)
#define PB_PREPW  (PB_PREPWC + 4096)   // total 16768

__global__ __launch_bounds__(256) void k_prep(
    const float* __restrict__ topic,
    const float* __restrict__ thiw, const float* __restrict__ thib,
    const float* __restrict__ thhw, const float* __restrict__ thhb,
    const float* __restrict__ wib, const float* __restrict__ whb,
    const float* __restrict__ xin, const float* __restrict__ hx,
    const float* __restrict__ wic, const float* __restrict__ whc,
    const float* __restrict__ wia, const float* __restrict__ wha,
    const float* __restrict__ liw, const float* __restrict__ lhw,
    const float* __restrict__ lib, const float* __restrict__ lhb) {
    int blk = blockIdx.x, t = threadIdx.x;
    if (blk < PB_ZERO) {
        int i = blk * 256 + t;
        if (i < 2 * Fn * Fn) g_M[i] = 0.f;
        if (i < 2 * Fn) g_cm[i] = 0.f;
    } else if (blk < PB_SCALES) {
        int b = blk - PB_ZERO;
        int c = t;
        int path = c >> 7, f = c & 127;
        const float* thw = path ? thhw : thiw;
        const float* thb = path ? thhb : thib;
        const float* wb  = path ? whb  : wib;
        float t0 = topic[b * 3 + 0], t1 = topic[b * 3 + 1], t2 = topic[b * 3 + 2];
        float s = 0.f;
#pragma unroll
        for (int tt = 0; tt < 3; tt++) {
            float th = thb[tt] + t0 * thw[tt * 3 + 0] + t1 * thw[tt * 3 + 1] + t2 * thw[tt * 3 + 2];
            s += th * wb[f * 3 + tt];
        }
        g_scale[b * 256 + c] = s;
    } else if (blk < PB_PREPX) {
        int v = blk - PB_SCALES;
        int p = v >> 12, bb = v & 4095;
        const float* src = p ? hx : xin;
        int base = bb * 1024 + t * 4;
        float4 d = *(const float4*)(src + base);
        uint2 lo, hi = split_pack4(d, lo);
        *(uint2*)(g_Xh + p * (Bn * INn) + base) = hi;
        *(uint2*)(g_Xl + p * (Bn * INn) + base) = lo;
    } else if (blk < PB_PREPWC) {
        int v = blk - PB_PREPX;
        int p = v >> 7, bb = v & 127;
        const float* src = p ? whc : wic;
        int base = bb * 1024 + t * 4;
        float4 d = *(const float4*)(src + base);
        uint2 lo, hi = split_pack4(d, lo);
        *(uint2*)(g_Vh + p * (Fn * INn) + base) = hi;
        *(uint2*)(g_Vl + p * (Fn * INn) + base) = lo;
    } else {
        int C = blk - PB_PREPWC;
        int k = t;
        int h = ((C >> 5) << 3) + (C & 7);
        int gate = (C >> 3) & 3;
        int j = gate * 1024 + h;
        float v;
        if (k < 128) v = wia[j * 128 + k] * liw[j];
        else         v = wha[j * 128 + (k - 128)] * lhw[j];
        float hi = __bfloat162float(__float2bfloat16(v));
        g_Wh[C * 256 + k] = __float2bfloat16(v);
        g_Wl[C * 256 + k] = __float2bfloat16(v - hi);
        if (k == 0) g_bcomb[j] = lib[j] + lhb[j];
    }
}

// ---------------------------------------------------------------------------
__global__ __launch_bounds__(256) void k_syrk(const float* __restrict__ wia,
                                              const float* __restrict__ wha) {
    int p = blockIdx.y;
    const float* A = p ? wha : wia;   // [4096, 128]
    __shared__ float sA[64 * 128];
    int tid = threadIdx.x;
    int f1 = (tid >> 4) * 8, f2 = (tid & 15) * 8;
    float acc[8][8];
#pragma unroll
    for (int i = 0; i < 8; i++)
#pragma unroll
        for (int k = 0; k < 8; k++) acc[i][k] = 0.f;
    float cs = 0.f;
    for (int jc = 0; jc < 2; jc++) {
        int j0 = blockIdx.x * 128 + jc * 64;
        for (int v = tid; v < 64 * 128 / 4; v += 256)
            ((float4*)sA)[v] = ((const float4*)(A + j0 * 128))[v];
        __syncthreads();
        for (int j = 0; j < 64; j++) {
            float l[8], r[8];
#pragma unroll
            for (int i = 0; i < 8; i++) { l[i] = sA[j * 128 + f1 + i]; r[i] = sA[j * 128 + f2 + i]; }
#pragma unroll
            for (int i = 0; i < 8; i++)
#pragma unroll
                for (int k = 0; k < 8; k++) acc[i][k] += l[i] * r[k];
        }
        if (tid < 128) {
            for (int j = 0; j < 64; j++) cs += sA[j * 128 + tid];
        }
        __syncthreads();
    }
#pragma unroll
    for (int i = 0; i < 8; i++)
#pragma unroll
        for (int k = 0; k < 8; k++)
            atomicAdd(&g_M[p * Fn * Fn + (f1 + i) * Fn + (f2 + k)], acc[i][k]);
    if (tid < 128) atomicAdd(&g_cm[p * Fn + tid], cs);
}

// ===========================================================================
// GEMM1 via mma.sync bf16 hi/lo: U[b,f] = (X @ W^T)*scale, per path.
// CTA 64(M) x 128(N=all F). K=1024 in 16 chunks of 64. 8 warps 2(M)x4(N).
// ===========================================================================
#define G1_STAGE 49152
#define G1_SMEM  (2 * G1_STAGE)

__global__ __launch_bounds__(256, 2) void k_gemm1_mma() {
    extern __shared__ char smem[];
    uint32_t sb = smem_u32(smem);
    const int tid = threadIdx.x, l = tid & 31, wid = tid >> 5;
    const int wm = wid & 1, wn = wid >> 1;
    const int rb = blockIdx.x, p = blockIdx.y;
    const __nv_bfloat16* Xh = g_Xh + p * (Bn * INn);
    const __nv_bfloat16* Xl = g_Xl + p * (Bn * INn);
    const __nv_bfloat16* Vh = g_Vh + p * (Fn * INn);
    const __nv_bfloat16* Vl = g_Vl + p * (Fn * INn);

    float acc[2][4][4];
#pragma unroll
    for (int a = 0; a < 2; a++)
#pragma unroll
        for (int b = 0; b < 4; b++)
#pragma unroll
            for (int c = 0; c < 4; c++) acc[a][b][c] = 0.f;

#pragma unroll 1
    for (int cc = -1; cc < 16; cc++) {
        int ci = cc + 1;
        if (ci < 16) {
            uint32_t stage = sb + (uint32_t)(ci & 1) * G1_STAGE;
#pragma unroll
            for (int it = 0; it < 2; it++) {         // A: 64 rows x 8 ch
                int v = tid + it * 256;
                int row = v >> 3, ch = v & 7;
                uint32_t soff = (uint32_t)((row * 8 + (ch ^ (row & 7))) << 4);
                cp_async16(stage + soff,        Xh + (rb * 64 + row) * 1024 + ci * 64 + ch * 8);
                cp_async16(stage + 8192 + soff, Xl + (rb * 64 + row) * 1024 + ci * 64 + ch * 8);
            }
#pragma unroll
            for (int it = 0; it < 4; it++) {         // B: 128 rows x 8 ch
                int v = tid + it * 256;
                int row = v >> 3, ch = v & 7;
                uint32_t soff = (uint32_t)((row * 8 + (ch ^ (row & 7))) << 4);
                cp_async16(stage + 16384 + soff, Vh + row * 1024 + ci * 64 + ch * 8);
                cp_async16(stage + 32768 + soff, Vl + row * 1024 + ci * 64 + ch * 8);
            }
            cp_commit();
        }
        if (cc < 0) continue;
        if (cc < 15) asm volatile("cp.async.wait_group 1;" ::: "memory");
        else         asm volatile("cp.async.wait_group 0;" ::: "memory");
        __syncthreads();

        uint32_t Ah = sb + (uint32_t)(cc & 1) * G1_STAGE;
        uint32_t Al = Ah + 8192, Bh = Ah + 16384, Bl = Ah + 32768;
#pragma unroll
        for (int ks = 0; ks < 4; ks++) {
            uint32_t a[2][4], bh[2][4], bl[2][4];
#pragma unroll
            for (int mi = 0; mi < 2; mi++) {
                int r0 = wm * 32 + mi * 16 + ((l >> 3) & 1) * 8 + (l & 7);
                int ch = ks * 2 + (l >> 4);
                ldsm4(a[mi], Ah + (uint32_t)((r0 * 8 + (ch ^ (r0 & 7))) << 4));
            }
#pragma unroll
            for (int nfp = 0; nfp < 2; nfp++) {
                int m = l >> 3;
                int nr = wn * 32 + nfp * 16 + ((m >> 1) << 3) + (l & 7);
                int ch = ks * 2 + (m & 1);
                uint32_t soff = (uint32_t)((nr * 8 + (ch ^ (nr & 7))) << 4);
                ldsm4(bh[nfp], Bh + soff);
                ldsm4(bl[nfp], Bl + soff);
            }
#pragma unroll
            for (int mi = 0; mi < 2; mi++)
#pragma unroll
                for (int nf = 0; nf < 4; nf++) {
                    mma16816(acc[mi][nf], a[mi], bh[nf >> 1][(nf & 1) * 2], bh[nf >> 1][(nf & 1) * 2 + 1]);
                    mma16816(acc[mi][nf], a[mi], bl[nf >> 1][(nf & 1) * 2], bl[nf >> 1][(nf & 1) * 2 + 1]);
                }
#pragma unroll
            for (int mi = 0; mi < 2; mi++) {         // reload A as lo, reuse regs
                int r0 = wm * 32 + mi * 16 + ((l >> 3) & 1) * 8 + (l & 7);
                int ch = ks * 2 + (l >> 4);
                ldsm4(a[mi], Al + (uint32_t)((r0 * 8 + (ch ^ (r0 & 7))) << 4));
            }
#pragma unroll
            for (int mi = 0; mi < 2; mi++)
#pragma unroll
                for (int nf = 0; nf < 4; nf++)
                    mma16816(acc[mi][nf], a[mi], bh[nf >> 1][(nf & 1) * 2], bh[nf >> 1][(nf & 1) * 2 + 1]);
        }
        __syncthreads();
    }

    // epilogue: multiply by scale, write g_U fp32
#pragma unroll
    for (int mi = 0; mi < 2; mi++)
#pragma unroll
        for (int rs = 0; rs < 2; rs++) {
            int row = rb * 64 + wm * 32 + mi * 16 + (l >> 2) + rs * 8;
#pragma unroll
            for (int nf = 0; nf < 4; nf++)
#pragma unroll
                for (int e = 0; e < 2; e++) {
                    int fcol = wn * 32 + nf * 8 + (l & 3) * 2 + e;
                    int idx = row * 256 + p * 128 + fcol;
                    g_U[idx] = acc[mi][nf][rs * 2 + e] * g_scale[idx];
                }
        }
}

// ---------------------------------------------------------------------------
// LN stats via quadratic form + fused prepU. Warp-parallel reduction:
// 3 syncthreads total (was ~65).
__global__ __launch_bounds__(128) void k_stats() {
    int b0 = blockIdx.x * 16;
    int t = threadIdx.x;   // 0..127
    int lane = t & 31, wi = t >> 5;
    __shared__ float su[16 * 256];
    __shared__ float part[2][4][16][2];   // [path][warp][row][q|dm]
    __shared__ float sstat[16][4];
    for (int v = t; v < 16 * 256 / 4; v += 128)
        ((float4*)su)[v] = ((const float4*)(g_U + b0 * 256))[v];
    __syncthreads();
#pragma unroll
    for (int p = 0; p < 2; p++) {
        float w[16];
#pragma unroll
        for (int r = 0; r < 16; r++) w[r] = 0.f;
        const float* M = g_M + p * Fn * Fn;
        for (int f2 = 0; f2 < 128; f2++) {
            float mc = M[f2 * 128 + t];
#pragma unroll
            for (int r = 0; r < 16; r++) w[r] += mc * su[r * 256 + p * 128 + f2];
        }
        float cm = g_cm[p * 128 + t];
#pragma unroll
        for (int r = 0; r < 16; r++) {
            float uv = su[r * 256 + p * 128 + t];
            float q = uv * w[r];
            float dm = uv * cm;
#pragma unroll
            for (int o = 16; o; o >>= 1) {
                q  += __shfl_xor_sync(0xffffffffu, q, o);
                dm += __shfl_xor_sync(0xffffffffu, dm, o);
            }
            if (lane == 0) { part[p][wi][r][0] = q; part[p][wi][r][1] = dm; }
        }
    }
    __syncthreads();
    if (t < 32) {
        int r = t & 15, p = t >> 4;
        float qs = part[p][0][r][0] + part[p][1][r][0] + part[p][2][r][0] + part[p][3][r][0];
        float ds = part[p][0][r][1] + part[p][1][r][1] + part[p][2][r][1] + part[p][3][r][1];
        float mu = ds * (1.f / 4096.f);
        float ex2 = qs * (1.f / 4096.f);
        sstat[r][2 * p] = mu;
        sstat[r][2 * p + 1] = rsqrtf(ex2 - mu * mu + EPS);
    }
    __syncthreads();
    // fused prepU: fold rstd, split hi/lo
#pragma unroll 1
    for (int r = 0; r < 16; r++) {
        float rsi = sstat[r][1], rsh = sstat[r][3];
#pragma unroll
        for (int half = 0; half < 2; half++) {
            int c = t + half * 128;
            float v = su[r * 256 + c] * (c < 128 ? rsi : rsh);
            float hi = __bfloat162float(__float2bfloat16(v));
            g_Uh[(b0 + r) * 256 + c] = __float2bfloat16(v);
            g_Ul[(b0 + r) * 256 + c] = __float2bfloat16(v - hi);
        }
    }
    if (t < 16)
        g_a12[b0 + t] = make_float2(sstat[t][0] * sstat[t][1], sstat[t][2] * sstat[t][3]);
}

// ===========================================================================
// GEMM2 via mma.sync bf16 hi/lo — single-load K-chunks (8 chunks of K=32),
// 3 combos in-loop. CTA 128x128, 8 warps 2(M)x4(N). 3 stages, distance-2.
// ===========================================================================
#define G2_STAGE 32768
#define G2_SMEM  (3 * G2_STAGE)   // 96 KB

__global__ __launch_bounds__(256, 2) void k_gemm2_mma(
    const float* __restrict__ liw, const float* __restrict__ lhw,
    const float* __restrict__ cx) {
    extern __shared__ char smem[];
    uint32_t sb = smem_u32(smem);
    const int tid = threadIdx.x, l = tid & 31, wid = tid >> 5;
    const int wm = wid & 1, wn = wid >> 1;
    const int hb = blockIdx.x, rb = blockIdx.y;

    float acc[4][4][4];
#pragma unroll
    for (int a = 0; a < 4; a++)
#pragma unroll
        for (int b = 0; b < 4; b++)
#pragma unroll
            for (int c = 0; c < 4; c++) acc[a][b][c] = 0.f;

#pragma unroll 1
    for (int c = -2; c < 8; c++) {
        int ci = c + 2;
        if (ci < 8) {
            uint32_t stage = sb + (uint32_t)(ci % 3) * G2_STAGE;
#pragma unroll
            for (int it = 0; it < 2; it++) {   // per array: 128 rows x 4 ch(16B)
                int v = tid + it * 256;
                int row = v >> 2, ch = v & 3;
                uint32_t soff = (uint32_t)((row * 4 + (ch ^ ((row >> 1) & 3))) << 4);
                cp_async16(stage + soff,         g_Uh + (rb * 128 + row) * 256 + ci * 32 + ch * 8);
                cp_async16(stage + 8192 + soff,  g_Ul + (rb * 128 + row) * 256 + ci * 32 + ch * 8);
                cp_async16(stage + 16384 + soff, g_Wh + (hb * 128 + row) * 256 + ci * 32 + ch * 8);
                cp_async16(stage + 24576 + soff, g_Wl + (hb * 128 + row) * 256 + ci * 32 + ch * 8);
            }
            cp_commit();
        }
        if (c < 0) continue;
        if (c < 6)       asm volatile("cp.async.wait_group 2;" ::: "memory");
        else if (c == 6) asm volatile("cp.async.wait_group 1;" ::: "memory");
        else             asm volatile("cp.async.wait_group 0;" ::: "memory");
        __syncthreads();

        uint32_t Ah = sb + (uint32_t)(c % 3) * G2_STAGE;
        uint32_t Al = Ah + 8192, Bh = Ah + 16384, Bl = Ah + 24576;
#pragma unroll
        for (int ks = 0; ks < 2; ks++) {
            uint32_t a[4][4], bh[2][4], bl[2][4];
#pragma unroll
            for (int mi = 0; mi < 4; mi++) {
                int r0 = wm * 64 + mi * 16 + ((l >> 3) & 1) * 8 + (l & 7);
                int ch = ks * 2 + (l >> 4);
                ldsm4(a[mi], Ah + (uint32_t)((r0 * 4 + (ch ^ ((r0 >> 1) & 3))) << 4));
            }
#pragma unroll
            for (int nfp = 0; nfp < 2; nfp++) {
                int m = l >> 3;
                int nr = wn * 32 + nfp * 16 + ((m >> 1) << 3) + (l & 7);
                int ch = ks * 2 + (m & 1);
                uint32_t soff = (uint32_t)((nr * 4 + (ch ^ ((nr >> 1) & 3))) << 4);
                ldsm4(bh[nfp], Bh + soff);
                ldsm4(bl[nfp], Bl + soff);
            }
#pragma unroll
            for (int mi = 0; mi < 4; mi++)
#pragma unroll
                for (int nf = 0; nf < 4; nf++) {
                    mma16816(acc[mi][nf], a[mi], bh[nf >> 1][(nf & 1) * 2], bh[nf >> 1][(nf & 1) * 2 + 1]);
                    mma16816(acc[mi][nf], a[mi], bl[nf >> 1][(nf & 1) * 2], bl[nf >> 1][(nf & 1) * 2 + 1]);
                }
#pragma unroll
            for (int mi = 0; mi < 4; mi++) {   // reload A as lo, reuse regs
                int r0 = wm * 64 + mi * 16 + ((l >> 3) & 1) * 8 + (l & 7);
                int ch = ks * 2 + (l >> 4);
                ldsm4(a[mi], Al + (uint32_t)((r0 * 4 + (ch ^ ((r0 >> 1) & 3))) << 4));
            }
#pragma unroll
            for (int mi = 0; mi < 4; mi++)
#pragma unroll
                for (int nf = 0; nf < 4; nf++)
                    mma16816(acc[mi][nf], a[mi], bh[nf >> 1][(nf & 1) * 2], bh[nf >> 1][(nf & 1) * 2 + 1]);
        }
        __syncthreads();
    }

    // ---- fused epilogue ----
    const int q = l & 3;
    float cliw[4][2], clhw[4][2], cbc[4][2];
#pragma unroll
    for (int g = 0; g < 4; g++)
#pragma unroll
        for (int e = 0; e < 2; e++) {
            int h = (hb * 4 + wn) * 8 + q * 2 + e;
            int j = g * 1024 + h;
            cliw[g][e] = liw[j];
            clhw[g][e] = lhw[j];
            cbc[g][e]  = g_bcomb[j];
        }
#pragma unroll
    for (int mi = 0; mi < 4; mi++) {
#pragma unroll
        for (int rs = 0; rs < 2; rs++) {
            int row = rb * 128 + wm * 64 + mi * 16 + (l >> 2) + rs * 8;
            float2 a12 = g_a12[row];
#pragma unroll
            for (int e = 0; e < 2; e++) {
                int h = (hb * 4 + wn) * 8 + q * 2 + e;
                float gv[4];
#pragma unroll
                for (int g = 0; g < 4; g++)
                    gv[g] = acc[mi][g][rs * 2 + e] + cbc[g][e]
                          - a12.x * cliw[g][e] - a12.y * clhw[g][e];
                float ig = 1.f / (1.f + __expf(-gv[0]));
                float fg = 1.f / (1.f + __expf(-gv[1]));
                float gg = tanhf(gv[2]);
                float og = 1.f / (1.f + __expf(-gv[3]));
                float cpre = fg * cx[row * Hn + h] + ig * gg;
                g_cpre[row * Hn + h] = cpre;
                g_oact[row * Hn + h] = og;
            }
        }
    }
}

// ---------------------------------------------------------------------------
__global__ __launch_bounds__(256) void k_final(const float* __restrict__ lcw,
                                               const float* __restrict__ lcb,
                                               float* __restrict__ out) {
    int b = blockIdx.x, t = threadIdx.x;
    float cl[4];
    float s = 0.f, s2 = 0.f;
#pragma unroll
    for (int i = 0; i < 4; i++) {
        cl[i] = g_cpre[b * Hn + t + i * 256];
        s += cl[i]; s2 += cl[i] * cl[i];
    }
#pragma unroll
    for (int o = 16; o; o >>= 1) {
        s  += __shfl_xor_sync(0xffffffffu, s, o);
        s2 += __shfl_xor_sync(0xffffffffu, s2, o);
    }
    __shared__ float sm1[8], sm2[8], bc[2];
    int wid = t >> 5, lane = t & 31;
    if (lane == 0) { sm1[wid] = s; sm2[wid] = s2; }
    __syncthreads();
    if (t == 0) {
        float ss = 0.f, ss2 = 0.f;
        for (int w = 0; w < 8; w++) { ss += sm1[w]; ss2 += sm2[w]; }
        float mu = ss * (1.f / 1024.f);
        float var = ss2 * (1.f / 1024.f) - mu * mu;
        bc[0] = mu; bc[1] = rsqrtf(var + EPS);
    }
    __syncthreads();
    float mu = bc[0], rstd = bc[1];
#pragma unroll
    for (int i = 0; i < 4; i++) {
        int h = t + i * 256;
        float cy = (cl[i] - mu) * rstd * lcw[h] + lcb[h];
        out[Bn * Hn + b * Hn + h] = cy;
        out[b * Hn + h] = g_oact[b * Hn + h] * tanhf(cy);
    }
}

// ---------------------------------------------------------------------------
extern "C" void kernel_launch(void* const* d_in, const int* in_sizes, int n_in,
                              void* d_out, int out_size) {
    const float* input_ = (const float*)d_in[0];
    const float* hx     = (const float*)d_in[1];
    const float* cx     = (const float*)d_in[2];
    const float* topic  = (const float*)d_in[3];
    const float* wia    = (const float*)d_in[4];
    const float* wib    = (const float*)d_in[5];
    const float* wic    = (const float*)d_in[6];
    const float* wha    = (const float*)d_in[7];
    const float* whb    = (const float*)d_in[8];
    const float* whc    = (const float*)d_in[9];
    const float* thiw   = (const float*)d_in[10];
    const float* thib   = (const float*)d_in[11];
    const float* thhw   = (const float*)d_in[12];
    const float* thhb   = (const float*)d_in[13];
    const float* liw    = (const float*)d_in[14];
    const float* lib    = (const float*)d_in[15];
    const float* lhw    = (const float*)d_in[16];
    const float* lhb    = (const float*)d_in[17];
    const float* lcw    = (const float*)d_in[18];
    const float* lcb    = (const float*)d_in[19];
    float* out = (float*)d_out;

    cudaFuncSetAttribute(k_gemm1_mma, cudaFuncAttributeMaxDynamicSharedMemorySize, G1_SMEM);
    cudaFuncSetAttribute(k_gemm2_mma, cudaFuncAttributeMaxDynamicSharedMemorySize, G2_SMEM);

    k_prep<<<PB_PREPW, 256>>>(topic, thiw, thib, thhw, thhb, wib, whb,
                              input_, hx, wic, whc, wia, wha, liw, lhw, lib, lhb);
    k_syrk<<<dim3(32, 2), 256>>>(wia, wha);
    k_gemm1_mma<<<dim3(64, 2), 256, G1_SMEM>>>();
    k_stats<<<256, 128>>>();
    k_gemm2_mma<<<dim3(32, 32), 256, G2_SMEM>>>(liw, lhw, cx);
    k_final<<<Bn, 256>>>(lcw, lcb, out);
}

// round 11
// speedup vs baseline: 2.2392x; 1.1686x over previous
#include <cuda_runtime.h>
#include <cuda_bf16.h>
#include <cstdint>
#include <math.h>

#define Bn 4096
#define INn 1024
#define Hn 1024
#define Fn 128
#define H4n 4096
#define EPS 1e-5f

// Scratch (static __device__ — no allocations allowed)
__device__ float g_scale[Bn * 256];   // [B][2F]
__device__ float g_U[Bn * 256];       // u fp32 (scale applied)
__device__ float g_Z[Bn * 256];       // Z = U·M^T per path
__device__ float g_M[2 * Fn * Fn];
__device__ float g_cm[2 * Fn];
__device__ float g_cpre[Bn * Hn];
__device__ float g_oact[Bn * Hn];
__device__ __nv_bfloat16 g_Uh[Bn * 256];    // gemm1 writes UNscaled; k_scaleU folds rstd in-place
__device__ __nv_bfloat16 g_Ul[Bn * 256];
__device__ __nv_bfloat16 g_Mh[2 * Fn * Fn];
__device__ __nv_bfloat16 g_Ml[2 * Fn * Fn];
__device__ __nv_bfloat16 g_Wh[H4n * 256];
__device__ __nv_bfloat16 g_Wl[H4n * 256];
__device__ __nv_bfloat16 g_Xh[2 * Bn * INn];
__device__ __nv_bfloat16 g_Xl[2 * Bn * INn];
__device__ __nv_bfloat16 g_Vh[2 * Fn * INn];
__device__ __nv_bfloat16 g_Vl[2 * Fn * INn];
__device__ float4 g_stats4[Bn];             // {rsi, rsh, mui*rsi, muh*rsh}
__device__ float g_bcomb[H4n];

// ============================ PTX helpers ===================================
__device__ __forceinline__ uint32_t smem_u32(const void* p) {
    uint32_t a;
    asm("{ .reg .u64 t; cvta.to.shared.u64 t, %1; cvt.u32.u64 %0, t; }" : "=r"(a) : "l"(p));
    return a;
}
__device__ __forceinline__ void cp_async16(uint32_t dst, const void* src) {
    asm volatile("cp.async.cg.shared.global [%0], [%1], 16;" :: "r"(dst), "l"(src) : "memory");
}
__device__ __forceinline__ void cp_commit() {
    asm volatile("cp.async.commit_group;" ::: "memory");
}
__device__ __forceinline__ void ldsm4(uint32_t* r, uint32_t a) {
    asm volatile("ldmatrix.sync.aligned.m8n8.x4.shared.b16 {%0,%1,%2,%3}, [%4];"
        : "=r"(r[0]), "=r"(r[1]), "=r"(r[2]), "=r"(r[3]) : "r"(a));
}
__device__ __forceinline__ void mma16816(float* d, const uint32_t* a, uint32_t b0, uint32_t b1) {
    asm volatile(
        "mma.sync.aligned.m16n8k16.row.col.f32.bf16.bf16.f32 "
        "{%0,%1,%2,%3}, {%4,%5,%6,%7}, {%8,%9}, {%0,%1,%2,%3};"
        : "+f"(d[0]), "+f"(d[1]), "+f"(d[2]), "+f"(d[3])
        : "r"(a[0]), "r"(a[1]), "r"(a[2]), "r"(a[3]), "r"(b0), "r"(b1));
}
__device__ __forceinline__ uint2 split_pack4(float4 d, uint2& lo) {
    __nv_bfloat16 h0 = __float2bfloat16(d.x), h1 = __float2bfloat16(d.y);
    __nv_bfloat16 h2 = __float2bfloat16(d.z), h3 = __float2bfloat16(d.w);
    __nv_bfloat16 l0 = __float2bfloat16(d.x - __bfloat162float(h0));
    __nv_bfloat16 l1 = __float2bfloat16(d.y - __bfloat162float(h1));
    __nv_bfloat16 l2 = __float2bfloat16(d.z - __bfloat162float(h2));
    __nv_bfloat16 l3 = __float2bfloat16(d.w - __bfloat162float(h3));
    uint2 hi;
    hi.x = (uint32_t)__bfloat16_as_ushort(h0) | ((uint32_t)__bfloat16_as_ushort(h1) << 16);
    hi.y = (uint32_t)__bfloat16_as_ushort(h2) | ((uint32_t)__bfloat16_as_ushort(h3) << 16);
    lo.x = (uint32_t)__bfloat16_as_ushort(l0) | ((uint32_t)__bfloat16_as_ushort(l1) << 16);
    lo.y = (uint32_t)__bfloat16_as_ushort(l2) | ((uint32_t)__bfloat16_as_ushort(l3) << 16);
    return hi;
}

// ===========================================================================
// Merged prep (verbatim from R10-passing kernel)
// ===========================================================================
#define PB_ZERO   128
#define PB_SCALES (PB_ZERO + 4096)
#define PB_PREPX  (PB_SCALES + 8192)
#define PB_PREPWC (PB_PREPX + 256)
#define PB_PREPW  (PB_PREPWC + 4096)

__global__ __launch_bounds__(256) void k_prep(
    const float* __restrict__ topic,
    const float* __restrict__ thiw, const float* __restrict__ thib,
    const float* __restrict__ thhw, const float* __restrict__ thhb,
    const float* __restrict__ wib, const float* __restrict__ whb,
    const float* __restrict__ xin, const float* __restrict__ hx,
    const float* __restrict__ wic, const float* __restrict__ whc,
    const float* __restrict__ wia, const float* __restrict__ wha,
    const float* __restrict__ liw, const float* __restrict__ lhw,
    const float* __restrict__ lib, const float* __restrict__ lhb) {
    int blk = blockIdx.x, t = threadIdx.x;
    if (blk < PB_ZERO) {
        int i = blk * 256 + t;
        if (i < 2 * Fn * Fn) g_M[i] = 0.f;
        if (i < 2 * Fn) g_cm[i] = 0.f;
    } else if (blk < PB_SCALES) {
        int b = blk - PB_ZERO;
        int c = t;
        int path = c >> 7, f = c & 127;
        const float* thw = path ? thhw : thiw;
        const float* thb = path ? thhb : thib;
        const float* wb  = path ? whb  : wib;
        float t0 = topic[b * 3 + 0], t1 = topic[b * 3 + 1], t2 = topic[b * 3 + 2];
        float s = 0.f;
#pragma unroll
        for (int tt = 0; tt < 3; tt++) {
            float th = thb[tt] + t0 * thw[tt * 3 + 0] + t1 * thw[tt * 3 + 1] + t2 * thw[tt * 3 + 2];
            s += th * wb[f * 3 + tt];
        }
        g_scale[b * 256 + c] = s;
    } else if (blk < PB_PREPX) {
        int v = blk - PB_SCALES;
        int p = v >> 12, bb = v & 4095;
        const float* src = p ? hx : xin;
        int base = bb * 1024 + t * 4;
        float4 d = *(const float4*)(src + base);
        uint2 lo, hi = split_pack4(d, lo);
        *(uint2*)(g_Xh + p * (Bn * INn) + base) = hi;
        *(uint2*)(g_Xl + p * (Bn * INn) + base) = lo;
    } else if (blk < PB_PREPWC) {
        int v = blk - PB_PREPX;
        int p = v >> 7, bb = v & 127;
        const float* src = p ? whc : wic;
        int base = bb * 1024 + t * 4;
        float4 d = *(const float4*)(src + base);
        uint2 lo, hi = split_pack4(d, lo);
        *(uint2*)(g_Vh + p * (Fn * INn) + base) = hi;
        *(uint2*)(g_Vl + p * (Fn * INn) + base) = lo;
    } else {
        int C = blk - PB_PREPWC;
        int k = t;
        int h = ((C >> 5) << 3) + (C & 7);
        int gate = (C >> 3) & 3;
        int j = gate * 1024 + h;
        float v;
        if (k < 128) v = wia[j * 128 + k] * liw[j];
        else         v = wha[j * 128 + (k - 128)] * lhw[j];
        float hi = __bfloat162float(__float2bfloat16(v));
        g_Wh[C * 256 + k] = __float2bfloat16(v);
        g_Wl[C * 256 + k] = __float2bfloat16(v - hi);
        if (k == 0) g_bcomb[j] = lib[j] + lhb[j];
    }
}

// ---------------------------------------------------------------------------
__global__ __launch_bounds__(256) void k_syrk(const float* __restrict__ wia,
                                              const float* __restrict__ wha) {
    int p = blockIdx.y;
    const float* A = p ? wha : wia;
    __shared__ float sA[64 * 128];
    int tid = threadIdx.x;
    int f1 = (tid >> 4) * 8, f2 = (tid & 15) * 8;
    float acc[8][8];
#pragma unroll
    for (int i = 0; i < 8; i++)
#pragma unroll
        for (int k = 0; k < 8; k++) acc[i][k] = 0.f;
    float cs = 0.f;
    for (int jc = 0; jc < 2; jc++) {
        int j0 = blockIdx.x * 128 + jc * 64;
        for (int v = tid; v < 64 * 128 / 4; v += 256)
            ((float4*)sA)[v] = ((const float4*)(A + j0 * 128))[v];
        __syncthreads();
        for (int j = 0; j < 64; j++) {
            float l[8], r[8];
#pragma unroll
            for (int i = 0; i < 8; i++) { l[i] = sA[j * 128 + f1 + i]; r[i] = sA[j * 128 + f2 + i]; }
#pragma unroll
            for (int i = 0; i < 8; i++)
#pragma unroll
                for (int k = 0; k < 8; k++) acc[i][k] += l[i] * r[k];
        }
        if (tid < 128) {
            for (int j = 0; j < 64; j++) cs += sA[j * 128 + tid];
        }
        __syncthreads();
    }
#pragma unroll
    for (int i = 0; i < 8; i++)
#pragma unroll
        for (int k = 0; k < 8; k++)
            atomicAdd(&g_M[p * Fn * Fn + (f1 + i) * Fn + (f2 + k)], acc[i][k]);
    if (tid < 128) atomicAdd(&g_cm[p * Fn + tid], cs);
}

// ---------------------------------------------------------------------------
__global__ __launch_bounds__(256) void k_prepM() {
    int base = blockIdx.x * 1024 + threadIdx.x * 4;   // 32 blocks x 1024
    float4 d = *(const float4*)(g_M + base);
    uint2 lo, hi = split_pack4(d, lo);
    *(uint2*)(g_Mh + base) = hi;
    *(uint2*)(g_Ml + base) = lo;
}

// ===========================================================================
// GEMM1 (validated mainloop; epilogue writes g_U fp32 + UNscaled Uh/Ul)
// ===========================================================================
#define G1_STAGE 49152
#define G1_SMEM  (2 * G1_STAGE)

__global__ __launch_bounds__(256, 2) void k_gemm1_mma() {
    extern __shared__ char smem[];
    uint32_t sb = smem_u32(smem);
    const int tid = threadIdx.x, l = tid & 31, wid = tid >> 5;
    const int wm = wid & 1, wn = wid >> 1;
    const int rb = blockIdx.x, p = blockIdx.y;
    const __nv_bfloat16* Xh = g_Xh + p * (Bn * INn);
    const __nv_bfloat16* Xl = g_Xl + p * (Bn * INn);
    const __nv_bfloat16* Vh = g_Vh + p * (Fn * INn);
    const __nv_bfloat16* Vl = g_Vl + p * (Fn * INn);

    float acc[2][4][4];
#pragma unroll
    for (int a = 0; a < 2; a++)
#pragma unroll
        for (int b = 0; b < 4; b++)
#pragma unroll
            for (int c = 0; c < 4; c++) acc[a][b][c] = 0.f;

#pragma unroll 1
    for (int cc = -1; cc < 16; cc++) {
        int ci = cc + 1;
        if (ci < 16) {
            uint32_t stage = sb + (uint32_t)(ci & 1) * G1_STAGE;
#pragma unroll
            for (int it = 0; it < 2; it++) {
                int v = tid + it * 256;
                int row = v >> 3, ch = v & 7;
                uint32_t soff = (uint32_t)((row * 8 + (ch ^ (row & 7))) << 4);
                cp_async16(stage + soff,        Xh + (rb * 64 + row) * 1024 + ci * 64 + ch * 8);
                cp_async16(stage + 8192 + soff, Xl + (rb * 64 + row) * 1024 + ci * 64 + ch * 8);
            }
#pragma unroll
            for (int it = 0; it < 4; it++) {
                int v = tid + it * 256;
                int row = v >> 3, ch = v & 7;
                uint32_t soff = (uint32_t)((row * 8 + (ch ^ (row & 7))) << 4);
                cp_async16(stage + 16384 + soff, Vh + row * 1024 + ci * 64 + ch * 8);
                cp_async16(stage + 32768 + soff, Vl + row * 1024 + ci * 64 + ch * 8);
            }
            cp_commit();
        }
        if (cc < 0) continue;
        if (cc < 15) asm volatile("cp.async.wait_group 1;" ::: "memory");
        else         asm volatile("cp.async.wait_group 0;" ::: "memory");
        __syncthreads();

        uint32_t Ah = sb + (uint32_t)(cc & 1) * G1_STAGE;
        uint32_t Al = Ah + 8192, Bh = Ah + 16384, Bl = Ah + 32768;
#pragma unroll
        for (int ks = 0; ks < 4; ks++) {
            uint32_t a[2][4], bh[2][4], bl[2][4];
#pragma unroll
            for (int mi = 0; mi < 2; mi++) {
                int r0 = wm * 32 + mi * 16 + ((l >> 3) & 1) * 8 + (l & 7);
                int ch = ks * 2 + (l >> 4);
                ldsm4(a[mi], Ah + (uint32_t)((r0 * 8 + (ch ^ (r0 & 7))) << 4));
            }
#pragma unroll
            for (int nfp = 0; nfp < 2; nfp++) {
                int m = l >> 3;
                int nr = wn * 32 + nfp * 16 + ((m >> 1) << 3) + (l & 7);
                int ch = ks * 2 + (m & 1);
                uint32_t soff = (uint32_t)((nr * 8 + (ch ^ (nr & 7))) << 4);
                ldsm4(bh[nfp], Bh + soff);
                ldsm4(bl[nfp], Bl + soff);
            }
#pragma unroll
            for (int mi = 0; mi < 2; mi++)
#pragma unroll
                for (int nf = 0; nf < 4; nf++) {
                    mma16816(acc[mi][nf], a[mi], bh[nf >> 1][(nf & 1) * 2], bh[nf >> 1][(nf & 1) * 2 + 1]);
                    mma16816(acc[mi][nf], a[mi], bl[nf >> 1][(nf & 1) * 2], bl[nf >> 1][(nf & 1) * 2 + 1]);
                }
#pragma unroll
            for (int mi = 0; mi < 2; mi++) {
                int r0 = wm * 32 + mi * 16 + ((l >> 3) & 1) * 8 + (l & 7);
                int ch = ks * 2 + (l >> 4);
                ldsm4(a[mi], Al + (uint32_t)((r0 * 8 + (ch ^ (r0 & 7))) << 4));
            }
#pragma unroll
            for (int mi = 0; mi < 2; mi++)
#pragma unroll
                for (int nf = 0; nf < 4; nf++)
                    mma16816(acc[mi][nf], a[mi], bh[nf >> 1][(nf & 1) * 2], bh[nf >> 1][(nf & 1) * 2 + 1]);
        }
        __syncthreads();
    }

#pragma unroll
    for (int mi = 0; mi < 2; mi++)
#pragma unroll
        for (int rs = 0; rs < 2; rs++) {
            int row = rb * 64 + wm * 32 + mi * 16 + (l >> 2) + rs * 8;
#pragma unroll
            for (int nf = 0; nf < 4; nf++) {
                int fcol0 = wn * 32 + nf * 8 + (l & 3) * 2;
                int idx = row * 256 + p * 128 + fcol0;
                float u0 = acc[mi][nf][rs * 2 + 0] * g_scale[idx];
                float u1 = acc[mi][nf][rs * 2 + 1] * g_scale[idx + 1];
                *(float2*)(g_U + idx) = make_float2(u0, u1);
                __nv_bfloat16 h0 = __float2bfloat16(u0), h1 = __float2bfloat16(u1);
                __nv_bfloat16 l0 = __float2bfloat16(u0 - __bfloat162float(h0));
                __nv_bfloat16 l1 = __float2bfloat16(u1 - __bfloat162float(h1));
                *(uint32_t*)(g_Uh + idx) =
                    (uint32_t)__bfloat16_as_ushort(h0) | ((uint32_t)__bfloat16_as_ushort(h1) << 16);
                *(uint32_t*)(g_Ul + idx) =
                    (uint32_t)__bfloat16_as_ushort(l0) | ((uint32_t)__bfloat16_as_ushort(l1) << 16);
            }
        }
}

// ===========================================================================
// STATGEMM: Z[b,f] = sum_k U[b,k] M[k,f] per path (M symmetric). K=128, 2 chunks.
// ===========================================================================
__global__ __launch_bounds__(256, 2) void k_statgemm() {
    extern __shared__ char smem[];
    uint32_t sb = smem_u32(smem);
    const int tid = threadIdx.x, l = tid & 31, wid = tid >> 5;
    const int wm = wid & 1, wn = wid >> 1;
    const int rb = blockIdx.x, p = blockIdx.y;

    float acc[2][4][4];
#pragma unroll
    for (int a = 0; a < 2; a++)
#pragma unroll
        for (int b = 0; b < 4; b++)
#pragma unroll
            for (int c = 0; c < 4; c++) acc[a][b][c] = 0.f;

#pragma unroll 1
    for (int cc = -1; cc < 2; cc++) {
        int ci = cc + 1;
        if (ci < 2) {
            uint32_t stage = sb + (uint32_t)(ci & 1) * G1_STAGE;
#pragma unroll
            for (int it = 0; it < 2; it++) {
                int v = tid + it * 256;
                int row = v >> 3, ch = v & 7;
                uint32_t soff = (uint32_t)((row * 8 + (ch ^ (row & 7))) << 4);
                cp_async16(stage + soff,        g_Uh + (rb * 64 + row) * 256 + p * 128 + ci * 64 + ch * 8);
                cp_async16(stage + 8192 + soff, g_Ul + (rb * 64 + row) * 256 + p * 128 + ci * 64 + ch * 8);
            }
#pragma unroll
            for (int it = 0; it < 4; it++) {
                int v = tid + it * 256;
                int row = v >> 3, ch = v & 7;
                uint32_t soff = (uint32_t)((row * 8 + (ch ^ (row & 7))) << 4);
                cp_async16(stage + 16384 + soff, g_Mh + p * (Fn * Fn) + row * 128 + ci * 64 + ch * 8);
                cp_async16(stage + 32768 + soff, g_Ml + p * (Fn * Fn) + row * 128 + ci * 64 + ch * 8);
            }
            cp_commit();
        }
        if (cc < 0) continue;
        if (cc < 1) asm volatile("cp.async.wait_group 1;" ::: "memory");
        else        asm volatile("cp.async.wait_group 0;" ::: "memory");
        __syncthreads();

        uint32_t Ah = sb + (uint32_t)(cc & 1) * G1_STAGE;
        uint32_t Al = Ah + 8192, Bh = Ah + 16384, Bl = Ah + 32768;
#pragma unroll
        for (int ks = 0; ks < 4; ks++) {
            uint32_t a[2][4], bh[2][4], bl[2][4];
#pragma unroll
            for (int mi = 0; mi < 2; mi++) {
                int r0 = wm * 32 + mi * 16 + ((l >> 3) & 1) * 8 + (l & 7);
                int ch = ks * 2 + (l >> 4);
                ldsm4(a[mi], Ah + (uint32_t)((r0 * 8 + (ch ^ (r0 & 7))) << 4));
            }
#pragma unroll
            for (int nfp = 0; nfp < 2; nfp++) {
                int m = l >> 3;
                int nr = wn * 32 + nfp * 16 + ((m >> 1) << 3) + (l & 7);
                int ch = ks * 2 + (m & 1);
                uint32_t soff = (uint32_t)((nr * 8 + (ch ^ (nr & 7))) << 4);
                ldsm4(bh[nfp], Bh + soff);
                ldsm4(bl[nfp], Bl + soff);
            }
#pragma unroll
            for (int mi = 0; mi < 2; mi++)
#pragma unroll
                for (int nf = 0; nf < 4; nf++) {
                    mma16816(acc[mi][nf], a[mi], bh[nf >> 1][(nf & 1) * 2], bh[nf >> 1][(nf & 1) * 2 + 1]);
                    mma16816(acc[mi][nf], a[mi], bl[nf >> 1][(nf & 1) * 2], bl[nf >> 1][(nf & 1) * 2 + 1]);
                }
#pragma unroll
            for (int mi = 0; mi < 2; mi++) {
                int r0 = wm * 32 + mi * 16 + ((l >> 3) & 1) * 8 + (l & 7);
                int ch = ks * 2 + (l >> 4);
                ldsm4(a[mi], Al + (uint32_t)((r0 * 8 + (ch ^ (r0 & 7))) << 4));
            }
#pragma unroll
            for (int mi = 0; mi < 2; mi++)
#pragma unroll
                for (int nf = 0; nf < 4; nf++)
                    mma16816(acc[mi][nf], a[mi], bh[nf >> 1][(nf & 1) * 2], bh[nf >> 1][(nf & 1) * 2 + 1]);
        }
        __syncthreads();
    }

#pragma unroll
    for (int mi = 0; mi < 2; mi++)
#pragma unroll
        for (int rs = 0; rs < 2; rs++) {
            int row = rb * 64 + wm * 32 + mi * 16 + (l >> 2) + rs * 8;
#pragma unroll
            for (int nf = 0; nf < 4; nf++) {
                int fcol0 = wn * 32 + nf * 8 + (l & 3) * 2;
                int idx = row * 256 + p * 128 + fcol0;
                *(float2*)(g_Z + idx) =
                    make_float2(acc[mi][nf][rs * 2 + 0], acc[mi][nf][rs * 2 + 1]);
            }
        }
}

// ---------------------------------------------------------------------------
// Stats finalize: q=<U,Z>, dm=<U,cm> per (row,path) warp; writes g_stats4.
__global__ __launch_bounds__(256) void k_stats2() {
    int t = threadIdx.x, lane = t & 31, w = t >> 5;
    int r = w >> 1, p = w & 1;
    int b = blockIdx.x * 4 + r;
    __shared__ float part[8][2];
    float4 u  = ((const float4*)(g_U + b * 256 + p * 128))[lane];
    float4 z  = ((const float4*)(g_Z + b * 256 + p * 128))[lane];
    float4 cm = ((const float4*)(g_cm + p * 128))[lane];
    float q  = u.x * z.x + u.y * z.y + u.z * z.z + u.w * z.w;
    float dm = u.x * cm.x + u.y * cm.y + u.z * cm.z + u.w * cm.w;
#pragma unroll
    for (int o = 16; o; o >>= 1) {
        q  += __shfl_xor_sync(0xffffffffu, q, o);
        dm += __shfl_xor_sync(0xffffffffu, dm, o);
    }
    if (lane == 0) { part[w][0] = q; part[w][1] = dm; }
    __syncthreads();
    if (t < 4) {
        float qi = part[t * 2 + 0][0], di = part[t * 2 + 0][1];
        float qh = part[t * 2 + 1][0], dh = part[t * 2 + 1][1];
        float mui = di * (1.f / 4096.f), muh = dh * (1.f / 4096.f);
        float rsi = rsqrtf(qi * (1.f / 4096.f) - mui * mui + EPS);
        float rsh = rsqrtf(qh * (1.f / 4096.f) - muh * muh + EPS);
        g_stats4[blockIdx.x * 4 + t] = make_float4(rsi, rsh, mui * rsi, muh * rsh);
    }
}

// ---------------------------------------------------------------------------
// Fold rstd into Uh/Ul in place (from g_U fp32, re-split) — restores gemm2's
// exact R10 operand semantics.
__global__ __launch_bounds__(256) void k_scaleU() {
    int b = blockIdx.x, k = threadIdx.x;
    float4 st = g_stats4[b];
    float v = g_U[b * 256 + k] * (k < 128 ? st.x : st.y);
    float hi = __bfloat162float(__float2bfloat16(v));
    g_Uh[b * 256 + k] = __float2bfloat16(v);
    g_Ul[b * 256 + k] = __float2bfloat16(v - hi);
}

// ===========================================================================
// GEMM2 (verbatim R10-passing mainloop + epilogue; a12 read from g_stats4.zw)
// ===========================================================================
#define G2_STAGE 32768
#define G2_SMEM  (3 * G2_STAGE)

__global__ __launch_bounds__(256, 2) void k_gemm2_mma(
    const float* __restrict__ liw, const float* __restrict__ lhw,
    const float* __restrict__ cx) {
    extern __shared__ char smem[];
    uint32_t sb = smem_u32(smem);
    const int tid = threadIdx.x, l = tid & 31, wid = tid >> 5;
    const int wm = wid & 1, wn = wid >> 1;
    const int hb = blockIdx.x, rb = blockIdx.y;

    float acc[4][4][4];
#pragma unroll
    for (int a = 0; a < 4; a++)
#pragma unroll
        for (int b = 0; b < 4; b++)
#pragma unroll
            for (int c = 0; c < 4; c++) acc[a][b][c] = 0.f;

#pragma unroll 1
    for (int c = -2; c < 8; c++) {
        int ci = c + 2;
        if (ci < 8) {
            uint32_t stage = sb + (uint32_t)(ci % 3) * G2_STAGE;
#pragma unroll
            for (int it = 0; it < 2; it++) {
                int v = tid + it * 256;
                int row = v >> 2, ch = v & 3;
                uint32_t soff = (uint32_t)((row * 4 + (ch ^ ((row >> 1) & 3))) << 4);
                cp_async16(stage + soff,         g_Uh + (rb * 128 + row) * 256 + ci * 32 + ch * 8);
                cp_async16(stage + 8192 + soff,  g_Ul + (rb * 128 + row) * 256 + ci * 32 + ch * 8);
                cp_async16(stage + 16384 + soff, g_Wh + (hb * 128 + row) * 256 + ci * 32 + ch * 8);
                cp_async16(stage + 24576 + soff, g_Wl + (hb * 128 + row) * 256 + ci * 32 + ch * 8);
            }
            cp_commit();
        }
        if (c < 0) continue;
        if (c < 6)       asm volatile("cp.async.wait_group 2;" ::: "memory");
        else if (c == 6) asm volatile("cp.async.wait_group 1;" ::: "memory");
        else             asm volatile("cp.async.wait_group 0;" ::: "memory");
        __syncthreads();

        uint32_t Ah = sb + (uint32_t)(c % 3) * G2_STAGE;
        uint32_t Al = Ah + 8192, Bh = Ah + 16384, Bl = Ah + 24576;
#pragma unroll
        for (int ks = 0; ks < 2; ks++) {
            uint32_t a[4][4], bh[2][4], bl[2][4];
#pragma unroll
            for (int mi = 0; mi < 4; mi++) {
                int r0 = wm * 64 + mi * 16 + ((l >> 3) & 1) * 8 + (l & 7);
                int ch = ks * 2 + (l >> 4);
                ldsm4(a[mi], Ah + (uint32_t)((r0 * 4 + (ch ^ ((r0 >> 1) & 3))) << 4));
            }
#pragma unroll
            for (int nfp = 0; nfp < 2; nfp++) {
                int m = l >> 3;
                int nr = wn * 32 + nfp * 16 + ((m >> 1) << 3) + (l & 7);
                int ch = ks * 2 + (m & 1);
                uint32_t soff = (uint32_t)((nr * 4 + (ch ^ ((nr >> 1) & 3))) << 4);
                ldsm4(bh[nfp], Bh + soff);
                ldsm4(bl[nfp], Bl + soff);
            }
#pragma unroll
            for (int mi = 0; mi < 4; mi++)
#pragma unroll
                for (int nf = 0; nf < 4; nf++) {
                    mma16816(acc[mi][nf], a[mi], bh[nf >> 1][(nf & 1) * 2], bh[nf >> 1][(nf & 1) * 2 + 1]);
                    mma16816(acc[mi][nf], a[mi], bl[nf >> 1][(nf & 1) * 2], bl[nf >> 1][(nf & 1) * 2 + 1]);
                }
#pragma unroll
            for (int mi = 0; mi < 4; mi++) {
                int r0 = wm * 64 + mi * 16 + ((l >> 3) & 1) * 8 + (l & 7);
                int ch = ks * 2 + (l >> 4);
                ldsm4(a[mi], Al + (uint32_t)((r0 * 4 + (ch ^ ((r0 >> 1) & 3))) << 4));
            }
#pragma unroll
            for (int mi = 0; mi < 4; mi++)
#pragma unroll
                for (int nf = 0; nf < 4; nf++)
                    mma16816(acc[mi][nf], a[mi], bh[nf >> 1][(nf & 1) * 2], bh[nf >> 1][(nf & 1) * 2 + 1]);
        }
        __syncthreads();
    }

    const int q = l & 3;
    float cliw[4][2], clhw[4][2], cbc[4][2];
#pragma unroll
    for (int g = 0; g < 4; g++)
#pragma unroll
        for (int e = 0; e < 2; e++) {
            int h = (hb * 4 + wn) * 8 + q * 2 + e;
            int j = g * 1024 + h;
            cliw[g][e] = liw[j];
            clhw[g][e] = lhw[j];
            cbc[g][e]  = g_bcomb[j];
        }
#pragma unroll
    for (int mi = 0; mi < 4; mi++) {
#pragma unroll
        for (int rs = 0; rs < 2; rs++) {
            int row = rb * 128 + wm * 64 + mi * 16 + (l >> 2) + rs * 8;
            float4 st = g_stats4[row];
#pragma unroll
            for (int e = 0; e < 2; e++) {
                int h = (hb * 4 + wn) * 8 + q * 2 + e;
                float gv[4];
#pragma unroll
                for (int g = 0; g < 4; g++)
                    gv[g] = acc[mi][g][rs * 2 + e] + cbc[g][e]
                          - st.z * cliw[g][e] - st.w * clhw[g][e];
                float ig = 1.f / (1.f + __expf(-gv[0]));
                float fg = 1.f / (1.f + __expf(-gv[1]));
                float gg = tanhf(gv[2]);
                float og = 1.f / (1.f + __expf(-gv[3]));
                float cpre = fg * cx[row * Hn + h] + ig * gg;
                g_cpre[row * Hn + h] = cpre;
                g_oact[row * Hn + h] = og;
            }
        }
    }
}

// ---------------------------------------------------------------------------
__global__ __launch_bounds__(256) void k_final(const float* __restrict__ lcw,
                                               const float* __restrict__ lcb,
                                               float* __restrict__ out) {
    int b = blockIdx.x, t = threadIdx.x;
    float cl[4];
    float s = 0.f, s2 = 0.f;
#pragma unroll
    for (int i = 0; i < 4; i++) {
        cl[i] = g_cpre[b * Hn + t + i * 256];
        s += cl[i]; s2 += cl[i] * cl[i];
    }
#pragma unroll
    for (int o = 16; o; o >>= 1) {
        s  += __shfl_xor_sync(0xffffffffu, s, o);
        s2 += __shfl_xor_sync(0xffffffffu, s2, o);
    }
    __shared__ float sm1[8], sm2[8], bc[2];
    int wid = t >> 5, lane = t & 31;
    if (lane == 0) { sm1[wid] = s; sm2[wid] = s2; }
    __syncthreads();
    if (t == 0) {
        float ss = 0.f, ss2 = 0.f;
        for (int w = 0; w < 8; w++) { ss += sm1[w]; ss2 += sm2[w]; }
        float mu = ss * (1.f / 1024.f);
        float var = ss2 * (1.f / 1024.f) - mu * mu;
        bc[0] = mu; bc[1] = rsqrtf(var + EPS);
    }
    __syncthreads();
    float mu = bc[0], rstd = bc[1];
#pragma unroll
    for (int i = 0; i < 4; i++) {
        int h = t + i * 256;
        float cy = (cl[i] - mu) * rstd * lcw[h] + lcb[h];
        out[Bn * Hn + b * Hn + h] = cy;
        out[b * Hn + h] = g_oact[b * Hn + h] * tanhf(cy);
    }
}

// ---------------------------------------------------------------------------
extern "C" void kernel_launch(void* const* d_in, const int* in_sizes, int n_in,
                              void* d_out, int out_size) {
    const float* input_ = (const float*)d_in[0];
    const float* hx     = (const float*)d_in[1];
    const float* cx     = (const float*)d_in[2];
    const float* topic  = (const float*)d_in[3];
    const float* wia    = (const float*)d_in[4];
    const float* wib    = (const float*)d_in[5];
    const float* wic    = (const float*)d_in[6];
    const float* wha    = (const float*)d_in[7];
    const float* whb    = (const float*)d_in[8];
    const float* whc    = (const float*)d_in[9];
    const float* thiw   = (const float*)d_in[10];
    const float* thib   = (const float*)d_in[11];
    const float* thhw   = (const float*)d_in[12];
    const float* thhb   = (const float*)d_in[13];
    const float* liw    = (const float*)d_in[14];
    const float* lib    = (const float*)d_in[15];
    const float* lhw    = (const float*)d_in[16];
    const float* lhb    = (const float*)d_in[17];
    const float* lcw    = (const float*)d_in[18];
    const float* lcb    = (const float*)d_in[19];
    float* out = (float*)d_out;

    cudaFuncSetAttribute(k_gemm1_mma, cudaFuncAttributeMaxDynamicSharedMemorySize, G1_SMEM);
    cudaFuncSetAttribute(k_statgemm, cudaFuncAttributeMaxDynamicSharedMemorySize, G1_SMEM);
    cudaFuncSetAttribute(k_gemm2_mma, cudaFuncAttributeMaxDynamicSharedMemorySize, G2_SMEM);

    k_prep<<<PB_PREPW, 256>>>(topic, thiw, thib, thhw, thhb, wib, whb,
                              input_, hx, wic, whc, wia, wha, liw, lhw, lib, lhb);
    k_syrk<<<dim3(32, 2), 256>>>(wia, wha);
    k_gemm1_mma<<<dim3(64, 2), 256, G1_SMEM>>>();
    k_prepM<<<32, 256>>>();
    k_statgemm<<<dim3(64, 2), 256, G1_SMEM>>>();
    k_stats2<<<1024, 256>>>();
    k_scaleU<<<Bn, 256>>>();
    k_gemm2_mma<<<dim3(32, 32), 256, G2_SMEM>>>(liw, lhw, cx);
    k_final<<<Bn, 256>>>(lcw, lcb, out);
}

// round 12
// speedup vs baseline: 2.2716x; 1.0145x over previous
#include <cuda_runtime.h>
#include <cuda_bf16.h>
#include <cstdint>
#include <math.h>

#define Bn 4096
#define INn 1024
#define Hn 1024
#define Fn 128
#define H4n 4096
#define EPS 1e-5f

// Scratch (static __device__ — no allocations allowed)
__device__ float g_scale[Bn * 256];   // [B][2F]
__device__ float g_U[Bn * 256];       // u fp32 (scale applied)
__device__ float g_Z[Bn * 256];       // Z = U·M^T per path
__device__ float g_M[2 * Fn * Fn];
__device__ float g_cm[2 * Fn];
__device__ float g_cpre[Bn * Hn];
__device__ float g_oact[Bn * Hn];
__device__ __nv_bfloat16 g_Uh[Bn * 256];    // gemm1 writes UNscaled; k_stats2 folds rstd in-place
__device__ __nv_bfloat16 g_Ul[Bn * 256];
__device__ __nv_bfloat16 g_Mh[2 * Fn * Fn];
__device__ __nv_bfloat16 g_Ml[2 * Fn * Fn];
__device__ __nv_bfloat16 g_Wh[H4n * 256];
__device__ __nv_bfloat16 g_Wl[H4n * 256];
__device__ __nv_bfloat16 g_Xh[2 * Bn * INn];
__device__ __nv_bfloat16 g_Xl[2 * Bn * INn];
__device__ __nv_bfloat16 g_Vh[2 * Fn * INn];
__device__ __nv_bfloat16 g_Vl[2 * Fn * INn];
__device__ float4 g_stats4[Bn];             // {rsi, rsh, mui*rsi, muh*rsh}
__device__ float g_bcomb[H4n];

// ============================ PTX helpers ===================================
__device__ __forceinline__ uint32_t smem_u32(const void* p) {
    uint32_t a;
    asm("{ .reg .u64 t; cvta.to.shared.u64 t, %1; cvt.u32.u64 %0, t; }" : "=r"(a) : "l"(p));
    return a;
}
__device__ __forceinline__ void cp_async16(uint32_t dst, const void* src) {
    asm volatile("cp.async.cg.shared.global [%0], [%1], 16;" :: "r"(dst), "l"(src) : "memory");
}
__device__ __forceinline__ void cp_commit() {
    asm volatile("cp.async.commit_group;" ::: "memory");
}
__device__ __forceinline__ void ldsm4(uint32_t* r, uint32_t a) {
    asm volatile("ldmatrix.sync.aligned.m8n8.x4.shared.b16 {%0,%1,%2,%3}, [%4];"
        : "=r"(r[0]), "=r"(r[1]), "=r"(r[2]), "=r"(r[3]) : "r"(a));
}
__device__ __forceinline__ void mma16816(float* d, const uint32_t* a, uint32_t b0, uint32_t b1) {
    asm volatile(
        "mma.sync.aligned.m16n8k16.row.col.f32.bf16.bf16.f32 "
        "{%0,%1,%2,%3}, {%4,%5,%6,%7}, {%8,%9}, {%0,%1,%2,%3};"
        : "+f"(d[0]), "+f"(d[1]), "+f"(d[2]), "+f"(d[3])
        : "r"(a[0]), "r"(a[1]), "r"(a[2]), "r"(a[3]), "r"(b0), "r"(b1));
}
__device__ __forceinline__ uint2 split_pack4(float4 d, uint2& lo) {
    __nv_bfloat16 h0 = __float2bfloat16(d.x), h1 = __float2bfloat16(d.y);
    __nv_bfloat16 h2 = __float2bfloat16(d.z), h3 = __float2bfloat16(d.w);
    __nv_bfloat16 l0 = __float2bfloat16(d.x - __bfloat162float(h0));
    __nv_bfloat16 l1 = __float2bfloat16(d.y - __bfloat162float(h1));
    __nv_bfloat16 l2 = __float2bfloat16(d.z - __bfloat162float(h2));
    __nv_bfloat16 l3 = __float2bfloat16(d.w - __bfloat162float(h3));
    uint2 hi;
    hi.x = (uint32_t)__bfloat16_as_ushort(h0) | ((uint32_t)__bfloat16_as_ushort(h1) << 16);
    hi.y = (uint32_t)__bfloat16_as_ushort(h2) | ((uint32_t)__bfloat16_as_ushort(h3) << 16);
    lo.x = (uint32_t)__bfloat16_as_ushort(l0) | ((uint32_t)__bfloat16_as_ushort(l1) << 16);
    lo.y = (uint32_t)__bfloat16_as_ushort(l2) | ((uint32_t)__bfloat16_as_ushort(l3) << 16);
    return hi;
}

// ===========================================================================
// Merged prep (verbatim from passing kernel)
// ===========================================================================
#define PB_ZERO   128
#define PB_SCALES (PB_ZERO + 4096)
#define PB_PREPX  (PB_SCALES + 8192)
#define PB_PREPWC (PB_PREPX + 256)
#define PB_PREPW  (PB_PREPWC + 4096)

__global__ __launch_bounds__(256) void k_prep(
    const float* __restrict__ topic,
    const float* __restrict__ thiw, const float* __restrict__ thib,
    const float* __restrict__ thhw, const float* __restrict__ thhb,
    const float* __restrict__ wib, const float* __restrict__ whb,
    const float* __restrict__ xin, const float* __restrict__ hx,
    const float* __restrict__ wic, const float* __restrict__ whc,
    const float* __restrict__ wia, const float* __restrict__ wha,
    const float* __restrict__ liw, const float* __restrict__ lhw,
    const float* __restrict__ lib, const float* __restrict__ lhb) {
    int blk = blockIdx.x, t = threadIdx.x;
    if (blk < PB_ZERO) {
        int i = blk * 256 + t;
        if (i < 2 * Fn * Fn) g_M[i] = 0.f;
        if (i < 2 * Fn) g_cm[i] = 0.f;
    } else if (blk < PB_SCALES) {
        int b = blk - PB_ZERO;
        int c = t;
        int path = c >> 7, f = c & 127;
        const float* thw = path ? thhw : thiw;
        const float* thb = path ? thhb : thib;
        const float* wb  = path ? whb  : wib;
        float t0 = topic[b * 3 + 0], t1 = topic[b * 3 + 1], t2 = topic[b * 3 + 2];
        float s = 0.f;
#pragma unroll
        for (int tt = 0; tt < 3; tt++) {
            float th = thb[tt] + t0 * thw[tt * 3 + 0] + t1 * thw[tt * 3 + 1] + t2 * thw[tt * 3 + 2];
            s += th * wb[f * 3 + tt];
        }
        g_scale[b * 256 + c] = s;
    } else if (blk < PB_PREPX) {
        int v = blk - PB_SCALES;
        int p = v >> 12, bb = v & 4095;
        const float* src = p ? hx : xin;
        int base = bb * 1024 + t * 4;
        float4 d = *(const float4*)(src + base);
        uint2 lo, hi = split_pack4(d, lo);
        *(uint2*)(g_Xh + p * (Bn * INn) + base) = hi;
        *(uint2*)(g_Xl + p * (Bn * INn) + base) = lo;
    } else if (blk < PB_PREPWC) {
        int v = blk - PB_PREPX;
        int p = v >> 7, bb = v & 127;
        const float* src = p ? whc : wic;
        int base = bb * 1024 + t * 4;
        float4 d = *(const float4*)(src + base);
        uint2 lo, hi = split_pack4(d, lo);
        *(uint2*)(g_Vh + p * (Fn * INn) + base) = hi;
        *(uint2*)(g_Vl + p * (Fn * INn) + base) = lo;
    } else {
        int C = blk - PB_PREPWC;
        int k = t;
        int h = ((C >> 5) << 3) + (C & 7);
        int gate = (C >> 3) & 3;
        int j = gate * 1024 + h;
        float v;
        if (k < 128) v = wia[j * 128 + k] * liw[j];
        else         v = wha[j * 128 + (k - 128)] * lhw[j];
        float hi = __bfloat162float(__float2bfloat16(v));
        g_Wh[C * 256 + k] = __float2bfloat16(v);
        g_Wl[C * 256 + k] = __float2bfloat16(v - hi);
        if (k == 0) g_bcomb[j] = lib[j] + lhb[j];
    }
}

// ---------------------------------------------------------------------------
__global__ __launch_bounds__(256) void k_syrk(const float* __restrict__ wia,
                                              const float* __restrict__ wha) {
    int p = blockIdx.y;
    const float* A = p ? wha : wia;
    __shared__ float sA[64 * 128];
    int tid = threadIdx.x;
    int f1 = (tid >> 4) * 8, f2 = (tid & 15) * 8;
    float acc[8][8];
#pragma unroll
    for (int i = 0; i < 8; i++)
#pragma unroll
        for (int k = 0; k < 8; k++) acc[i][k] = 0.f;
    float cs = 0.f;
    for (int jc = 0; jc < 2; jc++) {
        int j0 = blockIdx.x * 128 + jc * 64;
        for (int v = tid; v < 64 * 128 / 4; v += 256)
            ((float4*)sA)[v] = ((const float4*)(A + j0 * 128))[v];
        __syncthreads();
        for (int j = 0; j < 64; j++) {
            float l[8], r[8];
#pragma unroll
            for (int i = 0; i < 8; i++) { l[i] = sA[j * 128 + f1 + i]; r[i] = sA[j * 128 + f2 + i]; }
#pragma unroll
            for (int i = 0; i < 8; i++)
#pragma unroll
                for (int k = 0; k < 8; k++) acc[i][k] += l[i] * r[k];
        }
        if (tid < 128) {
            for (int j = 0; j < 64; j++) cs += sA[j * 128 + tid];
        }
        __syncthreads();
    }
#pragma unroll
    for (int i = 0; i < 8; i++)
#pragma unroll
        for (int k = 0; k < 8; k++)
            atomicAdd(&g_M[p * Fn * Fn + (f1 + i) * Fn + (f2 + k)], acc[i][k]);
    if (tid < 128) atomicAdd(&g_cm[p * Fn + tid], cs);
}

// ---------------------------------------------------------------------------
__global__ __launch_bounds__(256) void k_prepM() {
    int base = blockIdx.x * 1024 + threadIdx.x * 4;
    float4 d = *(const float4*)(g_M + base);
    uint2 lo, hi = split_pack4(d, lo);
    *(uint2*)(g_Mh + base) = hi;
    *(uint2*)(g_Ml + base) = lo;
}

// ===========================================================================
// GEMM1: CTA 32(M) x 128(N), grid (128, 2) — full-chip occupancy (2 CTAs/SM).
// 8 warps 1(M)x8(N), warp tile 32x16. K=1024 in 16 chunks of 64. 3 hi/lo
// combos per chunk. 2-stage dist-1. Stage: Ah 4K, Al 4K, Bh 16K, Bl 16K = 40K.
// ===========================================================================
#define G1_STAGE 40960
#define G1_SMEM  (2 * G1_STAGE)     // 81920
#define GS_STAGE 49152
#define GS_SMEM  (2 * GS_STAGE)     // 98304 (statgemm keeps old layout)

__global__ __launch_bounds__(256, 2) void k_gemm1_mma() {
    extern __shared__ char smem[];
    uint32_t sb = smem_u32(smem);
    const int tid = threadIdx.x, l = tid & 31, wid = tid >> 5;
    const int wn = wid;
    const int rb = blockIdx.x, p = blockIdx.y;
    const __nv_bfloat16* Xh = g_Xh + p * (Bn * INn);
    const __nv_bfloat16* Xl = g_Xl + p * (Bn * INn);
    const __nv_bfloat16* Vh = g_Vh + p * (Fn * INn);
    const __nv_bfloat16* Vl = g_Vl + p * (Fn * INn);

    float acc[2][2][4];
#pragma unroll
    for (int a = 0; a < 2; a++)
#pragma unroll
        for (int b = 0; b < 2; b++)
#pragma unroll
            for (int c = 0; c < 4; c++) acc[a][b][c] = 0.f;

#pragma unroll 1
    for (int cc = -1; cc < 16; cc++) {
        int ci = cc + 1;
        if (ci < 16) {
            uint32_t stage = sb + (uint32_t)(ci & 1) * G1_STAGE;
            {   // A: 32 rows x 8 ch = 256 chunks (1 per thread)
                int row = tid >> 3, ch = tid & 7;
                uint32_t soff = (uint32_t)((row * 8 + (ch ^ (row & 7))) << 4);
                cp_async16(stage + soff,        Xh + (rb * 32 + row) * 1024 + ci * 64 + ch * 8);
                cp_async16(stage + 4096 + soff, Xl + (rb * 32 + row) * 1024 + ci * 64 + ch * 8);
            }
#pragma unroll
            for (int it = 0; it < 4; it++) {   // B: 128 rows x 8 ch
                int v = tid + it * 256;
                int row = v >> 3, ch = v & 7;
                uint32_t soff = (uint32_t)((row * 8 + (ch ^ (row & 7))) << 4);
                cp_async16(stage + 8192 + soff,  Vh + row * 1024 + ci * 64 + ch * 8);
                cp_async16(stage + 24576 + soff, Vl + row * 1024 + ci * 64 + ch * 8);
            }
            cp_commit();
        }
        if (cc < 0) continue;
        if (cc < 15) asm volatile("cp.async.wait_group 1;" ::: "memory");
        else         asm volatile("cp.async.wait_group 0;" ::: "memory");
        __syncthreads();

        uint32_t Ah = sb + (uint32_t)(cc & 1) * G1_STAGE;
        uint32_t Al = Ah + 4096, Bh = Ah + 8192, Bl = Ah + 24576;
#pragma unroll
        for (int ks = 0; ks < 4; ks++) {
            uint32_t a[2][4], bh[4], bl[4];
#pragma unroll
            for (int mi = 0; mi < 2; mi++) {
                int r0 = mi * 16 + ((l >> 3) & 1) * 8 + (l & 7);
                int ch = ks * 2 + (l >> 4);
                ldsm4(a[mi], Ah + (uint32_t)((r0 * 8 + (ch ^ (r0 & 7))) << 4));
            }
            {
                int m = l >> 3;
                int nr = wn * 16 + ((m >> 1) << 3) + (l & 7);
                int ch = ks * 2 + (m & 1);
                uint32_t soff = (uint32_t)((nr * 8 + (ch ^ (nr & 7))) << 4);
                ldsm4(bh, Bh + soff);
                ldsm4(bl, Bl + soff);
            }
#pragma unroll
            for (int mi = 0; mi < 2; mi++)
#pragma unroll
                for (int nf = 0; nf < 2; nf++) {
                    mma16816(acc[mi][nf], a[mi], bh[nf * 2], bh[nf * 2 + 1]);
                    mma16816(acc[mi][nf], a[mi], bl[nf * 2], bl[nf * 2 + 1]);
                }
#pragma unroll
            for (int mi = 0; mi < 2; mi++) {   // reload A as lo
                int r0 = mi * 16 + ((l >> 3) & 1) * 8 + (l & 7);
                int ch = ks * 2 + (l >> 4);
                ldsm4(a[mi], Al + (uint32_t)((r0 * 8 + (ch ^ (r0 & 7))) << 4));
            }
#pragma unroll
            for (int mi = 0; mi < 2; mi++)
#pragma unroll
                for (int nf = 0; nf < 2; nf++)
                    mma16816(acc[mi][nf], a[mi], bh[nf * 2], bh[nf * 2 + 1]);
        }
        __syncthreads();
    }

    // epilogue: scale, write g_U fp32 + unscaled Uh/Ul
#pragma unroll
    for (int mi = 0; mi < 2; mi++)
#pragma unroll
        for (int rs = 0; rs < 2; rs++) {
            int row = rb * 32 + mi * 16 + (l >> 2) + rs * 8;
#pragma unroll
            for (int nf = 0; nf < 2; nf++) {
                int fcol0 = wn * 16 + nf * 8 + (l & 3) * 2;
                int idx = row * 256 + p * 128 + fcol0;
                float u0 = acc[mi][nf][rs * 2 + 0] * g_scale[idx];
                float u1 = acc[mi][nf][rs * 2 + 1] * g_scale[idx + 1];
                *(float2*)(g_U + idx) = make_float2(u0, u1);
                __nv_bfloat16 h0 = __float2bfloat16(u0), h1 = __float2bfloat16(u1);
                __nv_bfloat16 l0 = __float2bfloat16(u0 - __bfloat162float(h0));
                __nv_bfloat16 l1 = __float2bfloat16(u1 - __bfloat162float(h1));
                *(uint32_t*)(g_Uh + idx) =
                    (uint32_t)__bfloat16_as_ushort(h0) | ((uint32_t)__bfloat16_as_ushort(h1) << 16);
                *(uint32_t*)(g_Ul + idx) =
                    (uint32_t)__bfloat16_as_ushort(l0) | ((uint32_t)__bfloat16_as_ushort(l1) << 16);
            }
        }
}

// ===========================================================================
// STATGEMM: Z[b,f] = sum_k U[b,k] M[k,f] per path (unchanged, GS_STAGE layout)
// ===========================================================================
__global__ __launch_bounds__(256, 2) void k_statgemm() {
    extern __shared__ char smem[];
    uint32_t sb = smem_u32(smem);
    const int tid = threadIdx.x, l = tid & 31, wid = tid >> 5;
    const int wm = wid & 1, wn = wid >> 1;
    const int rb = blockIdx.x, p = blockIdx.y;

    float acc[2][4][4];
#pragma unroll
    for (int a = 0; a < 2; a++)
#pragma unroll
        for (int b = 0; b < 4; b++)
#pragma unroll
            for (int c = 0; c < 4; c++) acc[a][b][c] = 0.f;

#pragma unroll 1
    for (int cc = -1; cc < 2; cc++) {
        int ci = cc + 1;
        if (ci < 2) {
            uint32_t stage = sb + (uint32_t)(ci & 1) * GS_STAGE;
#pragma unroll
            for (int it = 0; it < 2; it++) {
                int v = tid + it * 256;
                int row = v >> 3, ch = v & 7;
                uint32_t soff = (uint32_t)((row * 8 + (ch ^ (row & 7))) << 4);
                cp_async16(stage + soff,        g_Uh + (rb * 64 + row) * 256 + p * 128 + ci * 64 + ch * 8);
                cp_async16(stage + 8192 + soff, g_Ul + (rb * 64 + row) * 256 + p * 128 + ci * 64 + ch * 8);
            }
#pragma unroll
            for (int it = 0; it < 4; it++) {
                int v = tid + it * 256;
                int row = v >> 3, ch = v & 7;
                uint32_t soff = (uint32_t)((row * 8 + (ch ^ (row & 7))) << 4);
                cp_async16(stage + 16384 + soff, g_Mh + p * (Fn * Fn) + row * 128 + ci * 64 + ch * 8);
                cp_async16(stage + 32768 + soff, g_Ml + p * (Fn * Fn) + row * 128 + ci * 64 + ch * 8);
            }
            cp_commit();
        }
        if (cc < 0) continue;
        if (cc < 1) asm volatile("cp.async.wait_group 1;" ::: "memory");
        else        asm volatile("cp.async.wait_group 0;" ::: "memory");
        __syncthreads();

        uint32_t Ah = sb + (uint32_t)(cc & 1) * GS_STAGE;
        uint32_t Al = Ah + 8192, Bh = Ah + 16384, Bl = Ah + 32768;
#pragma unroll
        for (int ks = 0; ks < 4; ks++) {
            uint32_t a[2][4], bh[2][4], bl[2][4];
#pragma unroll
            for (int mi = 0; mi < 2; mi++) {
                int r0 = wm * 32 + mi * 16 + ((l >> 3) & 1) * 8 + (l & 7);
                int ch = ks * 2 + (l >> 4);
                ldsm4(a[mi], Ah + (uint32_t)((r0 * 8 + (ch ^ (r0 & 7))) << 4));
            }
#pragma unroll
            for (int nfp = 0; nfp < 2; nfp++) {
                int m = l >> 3;
                int nr = wn * 32 + nfp * 16 + ((m >> 1) << 3) + (l & 7);
                int ch = ks * 2 + (m & 1);
                uint32_t soff = (uint32_t)((nr * 8 + (ch ^ (nr & 7))) << 4);
                ldsm4(bh[nfp], Bh + soff);
                ldsm4(bl[nfp], Bl + soff);
            }
#pragma unroll
            for (int mi = 0; mi < 2; mi++)
#pragma unroll
                for (int nf = 0; nf < 4; nf++) {
                    mma16816(acc[mi][nf], a[mi], bh[nf >> 1][(nf & 1) * 2], bh[nf >> 1][(nf & 1) * 2 + 1]);
                    mma16816(acc[mi][nf], a[mi], bl[nf >> 1][(nf & 1) * 2], bl[nf >> 1][(nf & 1) * 2 + 1]);
                }
#pragma unroll
            for (int mi = 0; mi < 2; mi++) {
                int r0 = wm * 32 + mi * 16 + ((l >> 3) & 1) * 8 + (l & 7);
                int ch = ks * 2 + (l >> 4);
                ldsm4(a[mi], Al + (uint32_t)((r0 * 8 + (ch ^ (r0 & 7))) << 4));
            }
#pragma unroll
            for (int mi = 0; mi < 2; mi++)
#pragma unroll
                for (int nf = 0; nf < 4; nf++)
                    mma16816(acc[mi][nf], a[mi], bh[nf >> 1][(nf & 1) * 2], bh[nf >> 1][(nf & 1) * 2 + 1]);
        }
        __syncthreads();
    }

#pragma unroll
    for (int mi = 0; mi < 2; mi++)
#pragma unroll
        for (int rs = 0; rs < 2; rs++) {
            int row = rb * 64 + wm * 32 + mi * 16 + (l >> 2) + rs * 8;
#pragma unroll
            for (int nf = 0; nf < 4; nf++) {
                int fcol0 = wn * 32 + nf * 8 + (l & 3) * 2;
                int idx = row * 256 + p * 128 + fcol0;
                *(float2*)(g_Z + idx) =
                    make_float2(acc[mi][nf][rs * 2 + 0], acc[mi][nf][rs * 2 + 1]);
            }
        }
}

// ---------------------------------------------------------------------------
// Stats finalize + FUSED rstd fold into Uh/Ul (was separate k_scaleU).
__global__ __launch_bounds__(256) void k_stats2() {
    int t = threadIdx.x, lane = t & 31, w = t >> 5;
    int r = w >> 1, p = w & 1;
    int b0 = blockIdx.x * 4;
    int b = b0 + r;
    __shared__ float part[8][2];
    __shared__ float4 sst[4];
    float4 u  = ((const float4*)(g_U + b * 256 + p * 128))[lane];
    float4 z  = ((const float4*)(g_Z + b * 256 + p * 128))[lane];
    float4 cm = ((const float4*)(g_cm + p * 128))[lane];
    float q  = u.x * z.x + u.y * z.y + u.z * z.z + u.w * z.w;
    float dm = u.x * cm.x + u.y * cm.y + u.z * cm.z + u.w * cm.w;
#pragma unroll
    for (int o = 16; o; o >>= 1) {
        q  += __shfl_xor_sync(0xffffffffu, q, o);
        dm += __shfl_xor_sync(0xffffffffu, dm, o);
    }
    if (lane == 0) { part[w][0] = q; part[w][1] = dm; }
    __syncthreads();
    if (t < 4) {
        float qi = part[t * 2 + 0][0], di = part[t * 2 + 0][1];
        float qh = part[t * 2 + 1][0], dh = part[t * 2 + 1][1];
        float mui = di * (1.f / 4096.f), muh = dh * (1.f / 4096.f);
        float rsi = rsqrtf(qi * (1.f / 4096.f) - mui * mui + EPS);
        float rsh = rsqrtf(qh * (1.f / 4096.f) - muh * muh + EPS);
        float4 sv = make_float4(rsi, rsh, mui * rsi, muh * rsh);
        g_stats4[b0 + t] = sv;
        sst[t] = sv;
    }
    __syncthreads();
    // fold rstd into Uh/Ul for these 4 rows
#pragma unroll
    for (int i = 0; i < 4; i++) {
        int idx = i * 256 + t;              // 0..1023
        int rr = idx >> 8, col = idx & 255;
        float4 sv = sst[rr];
        float v = g_U[(b0 + rr) * 256 + col] * (col < 128 ? sv.x : sv.y);
        float hi = __bfloat162float(__float2bfloat16(v));
        g_Uh[(b0 + rr) * 256 + col] = __float2bfloat16(v);
        g_Ul[(b0 + rr) * 256 + col] = __float2bfloat16(v - hi);
    }
}

// ===========================================================================
// GEMM2 (verbatim validated mainloop + epilogue; a12 from g_stats4.zw)
// ===========================================================================
#define G2_STAGE 32768
#define G2_SMEM  (3 * G2_STAGE)

__global__ __launch_bounds__(256, 2) void k_gemm2_mma(
    const float* __restrict__ liw, const float* __restrict__ lhw,
    const float* __restrict__ cx) {
    extern __shared__ char smem[];
    uint32_t sb = smem_u32(smem);
    const int tid = threadIdx.x, l = tid & 31, wid = tid >> 5;
    const int wm = wid & 1, wn = wid >> 1;
    const int hb = blockIdx.x, rb = blockIdx.y;

    float acc[4][4][4];
#pragma unroll
    for (int a = 0; a < 4; a++)
#pragma unroll
        for (int b = 0; b < 4; b++)
#pragma unroll
            for (int c = 0; c < 4; c++) acc[a][b][c] = 0.f;

#pragma unroll 1
    for (int c = -2; c < 8; c++) {
        int ci = c + 2;
        if (ci < 8) {
            uint32_t stage = sb + (uint32_t)(ci % 3) * G2_STAGE;
#pragma unroll
            for (int it = 0; it < 2; it++) {
                int v = tid + it * 256;
                int row = v >> 2, ch = v & 3;
                uint32_t soff = (uint32_t)((row * 4 + (ch ^ ((row >> 1) & 3))) << 4);
                cp_async16(stage + soff,         g_Uh + (rb * 128 + row) * 256 + ci * 32 + ch * 8);
                cp_async16(stage + 8192 + soff,  g_Ul + (rb * 128 + row) * 256 + ci * 32 + ch * 8);
                cp_async16(stage + 16384 + soff, g_Wh + (hb * 128 + row) * 256 + ci * 32 + ch * 8);
                cp_async16(stage + 24576 + soff, g_Wl + (hb * 128 + row) * 256 + ci * 32 + ch * 8);
            }
            cp_commit();
        }
        if (c < 0) continue;
        if (c < 6)       asm volatile("cp.async.wait_group 2;" ::: "memory");
        else if (c == 6) asm volatile("cp.async.wait_group 1;" ::: "memory");
        else             asm volatile("cp.async.wait_group 0;" ::: "memory");
        __syncthreads();

        uint32_t Ah = sb + (uint32_t)(c % 3) * G2_STAGE;
        uint32_t Al = Ah + 8192, Bh = Ah + 16384, Bl = Ah + 24576;
#pragma unroll
        for (int ks = 0; ks < 2; ks++) {
            uint32_t a[4][4], bh[2][4], bl[2][4];
#pragma unroll
            for (int mi = 0; mi < 4; mi++) {
                int r0 = wm * 64 + mi * 16 + ((l >> 3) & 1) * 8 + (l & 7);
                int ch = ks * 2 + (l >> 4);
                ldsm4(a[mi], Ah + (uint32_t)((r0 * 4 + (ch ^ ((r0 >> 1) & 3))) << 4));
            }
#pragma unroll
            for (int nfp = 0; nfp < 2; nfp++) {
                int m = l >> 3;
                int nr = wn * 32 + nfp * 16 + ((m >> 1) << 3) + (l & 7);
                int ch = ks * 2 + (m & 1);
                uint32_t soff = (uint32_t)((nr * 4 + (ch ^ ((nr >> 1) & 3))) << 4);
                ldsm4(bh[nfp], Bh + soff);
                ldsm4(bl[nfp], Bl + soff);
            }
#pragma unroll
            for (int mi = 0; mi < 4; mi++)
#pragma unroll
                for (int nf = 0; nf < 4; nf++) {
                    mma16816(acc[mi][nf], a[mi], bh[nf >> 1][(nf & 1) * 2], bh[nf >> 1][(nf & 1) * 2 + 1]);
                    mma16816(acc[mi][nf], a[mi], bl[nf >> 1][(nf & 1) * 2], bl[nf >> 1][(nf & 1) * 2 + 1]);
                }
#pragma unroll
            for (int mi = 0; mi < 4; mi++) {
                int r0 = wm * 64 + mi * 16 + ((l >> 3) & 1) * 8 + (l & 7);
                int ch = ks * 2 + (l >> 4);
                ldsm4(a[mi], Al + (uint32_t)((r0 * 4 + (ch ^ ((r0 >> 1) & 3))) << 4));
            }
#pragma unroll
            for (int mi = 0; mi < 4; mi++)
#pragma unroll
                for (int nf = 0; nf < 4; nf++)
                    mma16816(acc[mi][nf], a[mi], bh[nf >> 1][(nf & 1) * 2], bh[nf >> 1][(nf & 1) * 2 + 1]);
        }
        __syncthreads();
    }

    const int q = l & 3;
    float cliw[4][2], clhw[4][2], cbc[4][2];
#pragma unroll
    for (int g = 0; g < 4; g++)
#pragma unroll
        for (int e = 0; e < 2; e++) {
            int h = (hb * 4 + wn) * 8 + q * 2 + e;
            int j = g * 1024 + h;
            cliw[g][e] = liw[j];
            clhw[g][e] = lhw[j];
            cbc[g][e]  = g_bcomb[j];
        }
#pragma unroll
    for (int mi = 0; mi < 4; mi++) {
#pragma unroll
        for (int rs = 0; rs < 2; rs++) {
            int row = rb * 128 + wm * 64 + mi * 16 + (l >> 2) + rs * 8;
            float4 st = g_stats4[row];
#pragma unroll
            for (int e = 0; e < 2; e++) {
                int h = (hb * 4 + wn) * 8 + q * 2 + e;
                float gv[4];
#pragma unroll
                for (int g = 0; g < 4; g++)
                    gv[g] = acc[mi][g][rs * 2 + e] + cbc[g][e]
                          - st.z * cliw[g][e] - st.w * clhw[g][e];
                float ig = 1.f / (1.f + __expf(-gv[0]));
                float fg = 1.f / (1.f + __expf(-gv[1]));
                float gg = tanhf(gv[2]);
                float og = 1.f / (1.f + __expf(-gv[3]));
                float cpre = fg * cx[row * Hn + h] + ig * gg;
                g_cpre[row * Hn + h] = cpre;
                g_oact[row * Hn + h] = og;
            }
        }
    }
}

// ---------------------------------------------------------------------------
// Final LN: warp-per-row, no block syncs, float4 I/O. Grid 512 x 256 threads.
__global__ __launch_bounds__(256) void k_final(const float* __restrict__ lcw,
                                               const float* __restrict__ lcb,
                                               float* __restrict__ out) {
    int t = threadIdx.x, lane = t & 31, w = t >> 5;
    int b = blockIdx.x * 8 + w;
    const float4* cp4 = (const float4*)(g_cpre + b * Hn);
    const float4* oa4 = (const float4*)(g_oact + b * Hn);
    float4 c[8];
    float s = 0.f, s2 = 0.f;
#pragma unroll
    for (int i = 0; i < 8; i++) {
        c[i] = cp4[i * 32 + lane];
        s  += c[i].x + c[i].y + c[i].z + c[i].w;
        s2 += c[i].x * c[i].x + c[i].y * c[i].y + c[i].z * c[i].z + c[i].w * c[i].w;
    }
#pragma unroll
    for (int o = 16; o; o >>= 1) {
        s  += __shfl_xor_sync(0xffffffffu, s, o);
        s2 += __shfl_xor_sync(0xffffffffu, s2, o);
    }
    float mu = s * (1.f / 1024.f);
    float rstd = rsqrtf(s2 * (1.f / 1024.f) - mu * mu + EPS);
#pragma unroll
    for (int i = 0; i < 8; i++) {
        int h4 = i * 32 + lane;
        float4 wv = ((const float4*)lcw)[h4];
        float4 bv = ((const float4*)lcb)[h4];
        float4 ov = oa4[h4];
        float4 cy, hy;
        cy.x = (c[i].x - mu) * rstd * wv.x + bv.x;  hy.x = ov.x * tanhf(cy.x);
        cy.y = (c[i].y - mu) * rstd * wv.y + bv.y;  hy.y = ov.y * tanhf(cy.y);
        cy.z = (c[i].z - mu) * rstd * wv.z + bv.z;  hy.z = ov.z * tanhf(cy.z);
        cy.w = (c[i].w - mu) * rstd * wv.w + bv.w;  hy.w = ov.w * tanhf(cy.w);
        ((float4*)(out + Bn * Hn + b * Hn))[h4] = cy;
        ((float4*)(out + b * Hn))[h4] = hy;
    }
}

// ---------------------------------------------------------------------------
extern "C" void kernel_launch(void* const* d_in, const int* in_sizes, int n_in,
                              void* d_out, int out_size) {
    const float* input_ = (const float*)d_in[0];
    const float* hx     = (const float*)d_in[1];
    const float* cx     = (const float*)d_in[2];
    const float* topic  = (const float*)d_in[3];
    const float* wia    = (const float*)d_in[4];
    const float* wib    = (const float*)d_in[5];
    const float* wic    = (const float*)d_in[6];
    const float* wha    = (const float*)d_in[7];
    const float* whb    = (const float*)d_in[8];
    const float* whc    = (const float*)d_in[9];
    const float* thiw   = (const float*)d_in[10];
    const float* thib   = (const float*)d_in[11];
    const float* thhw   = (const float*)d_in[12];
    const float* thhb   = (const float*)d_in[13];
    const float* liw    = (const float*)d_in[14];
    const float* lib    = (const float*)d_in[15];
    const float* lhw    = (const float*)d_in[16];
    const float* lhb    = (const float*)d_in[17];
    const float* lcw    = (const float*)d_in[18];
    const float* lcb    = (const float*)d_in[19];
    float* out = (float*)d_out;

    cudaFuncSetAttribute(k_gemm1_mma, cudaFuncAttributeMaxDynamicSharedMemorySize, G1_SMEM);
    cudaFuncSetAttribute(k_statgemm, cudaFuncAttributeMaxDynamicSharedMemorySize, GS_SMEM);
    cudaFuncSetAttribute(k_gemm2_mma, cudaFuncAttributeMaxDynamicSharedMemorySize, G2_SMEM);

    k_prep<<<PB_PREPW, 256>>>(topic, thiw, thib, thhw, thhb, wib, whb,
                              input_, hx, wic, whc, wia, wha, liw, lhw, lib, lhb);
    k_syrk<<<dim3(32, 2), 256>>>(wia, wha);
    k_gemm1_mma<<<dim3(128, 2), 256, G1_SMEM>>>();
    k_prepM<<<32, 256>>>();
    k_statgemm<<<dim3(64, 2), 256, GS_SMEM>>>();
    k_stats2<<<1024, 256>>>();
    k_gemm2_mma<<<dim3(32, 32), 256, G2_SMEM>>>(liw, lhw, cx);
    k_final<<<512, 256>>>(lcw, lcb, out);
}